// round 8
// baseline (speedup 1.0000x reference)
#include <cuda_runtime.h>

typedef unsigned long long U64;

// ---------------- static device scratch ----------------
__device__ float g_xp[16777216];   // [2][64][1024][128] gate pre-activations
__device__ float g_h0[4194304];    // [64][1024][64]
__device__ float g_h1[4194304];    // [64][1024][64]
__device__ float g_part1[8388608]; // [64][64][2048] fc1 split-K partials
__device__ float g_hidden[131072]; // [64][2048]
__device__ float g_part2[2359296]; // [4][64][9216] fc2 split-K partials

// ---------------- helpers ----------------
__device__ __forceinline__ void ffma2(U64 &acc, U64 a, U64 b){
    asm("fma.rn.f32x2 %0, %1, %2, %0;" : "+l"(acc) : "l"(a), "l"(b));
}
__device__ __forceinline__ U64 add2(U64 a, U64 b){
    U64 r; asm("add.rn.f32x2 %0, %1, %2;" : "=l"(r) : "l"(a), "l"(b)); return r;
}
__device__ __forceinline__ float2 unpk(U64 v){
    float2 r; asm("mov.b64 {%0, %1}, %2;" : "=f"(r.x), "=f"(r.y) : "l"(v)); return r;
}
__device__ __forceinline__ U64 pack2(float lo, float hi){
    U64 r; asm("mov.b64 %0, {%1, %2};" : "=l"(r) : "f"(lo), "f"(hi)); return r;
}
__device__ __forceinline__ float sum2(U64 v){ float2 r = unpk(v); return r.x + r.y; }
__device__ __forceinline__ float fex2(float x){ float r; asm("ex2.approx.ftz.f32 %0, %1;" : "=f"(r) : "f"(x)); return r; }
__device__ __forceinline__ float frcp(float x){ float r; asm("rcp.approx.ftz.f32 %0, %1;" : "=f"(r) : "f"(x)); return r; }
__device__ __forceinline__ float sigf (float x){ return frcp(1.0f + fex2(-1.4426950408889634f * x)); }
__device__ __forceinline__ float tanhx(float x){ return fmaf(-2.0f, frcp(1.0f + fex2(2.8853900817779268f * x)), 1.0f); }

#define TW 132   // padded smem row stride (floats) for xproj kernels

// ---------------- xproj layer 0: tiled, K=9 ----------------
__global__ void __launch_bounds__(256) xproj0_kernel(const float* __restrict__ x,
    const float* __restrict__ wf, const float* __restrict__ bif, const float* __restrict__ bhf,
    const float* __restrict__ wr, const float* __restrict__ bir, const float* __restrict__ bhr)
{
    __shared__ float ws[9 * TW];
    __shared__ float fs[9 * TW];
    const int tid = threadIdx.x;
    const int s0 = blockIdx.x * 64;
    const int b  = blockIdx.y;
    const int d  = blockIdx.z;
    const float* w  = d ? wr : wf;
    const float* bi = d ? bir : bif;
    const float* bh = d ? bhr : bhf;

    if (tid < 128){
        const float* src = w + tid * 9;
        #pragma unroll
        for (int k = 0; k < 9; k++) ws[k * TW + tid] = src[k];
    } else if (tid < 192){
        int r = tid - 128;
        int s = s0 + r;
        int tsrc = d ? (1023 - s) : s;
        const float* src = x + ((size_t)b * 1024 + tsrc) * 9;
        #pragma unroll
        for (int k = 0; k < 9; k++){
            float v = src[k];
            *(float2*)&fs[k * TW + 2 * r] = make_float2(v, v);
        }
    }
    __syncthreads();

    const int nq = tid & 15;
    const int bq = tid >> 4;
    U64 acc[4][4];
    #pragma unroll
    for (int i = 0; i < 4; i++)
        #pragma unroll
        for (int j = 0; j < 4; j++) acc[i][j] = 0ull;

    #pragma unroll
    for (int kk = 0; kk < 9; kk++){
        ulonglong2 wa = *(const ulonglong2*)&ws[kk*TW + nq*4];
        ulonglong2 wb = *(const ulonglong2*)&ws[kk*TW + 64 + nq*4];
        ulonglong2 xa = *(const ulonglong2*)&fs[kk*TW + bq*8];
        ulonglong2 xc = *(const ulonglong2*)&fs[kk*TW + bq*8 + 4];
        U64 xv0 = xa.x, xv1 = xa.y, xv2 = xc.x, xv3 = xc.y;
        ffma2(acc[0][0], xv0, wa.x); ffma2(acc[0][1], xv0, wa.y);
        ffma2(acc[0][2], xv0, wb.x); ffma2(acc[0][3], xv0, wb.y);
        ffma2(acc[1][0], xv1, wa.x); ffma2(acc[1][1], xv1, wa.y);
        ffma2(acc[1][2], xv1, wb.x); ffma2(acc[1][3], xv1, wb.y);
        ffma2(acc[2][0], xv2, wa.x); ffma2(acc[2][1], xv2, wa.y);
        ffma2(acc[2][2], xv2, wb.x); ffma2(acc[2][3], xv2, wb.y);
        ffma2(acc[3][0], xv3, wa.x); ffma2(acc[3][1], xv3, wa.y);
        ffma2(acc[3][2], xv3, wb.x); ffma2(acc[3][3], xv3, wb.y);
    }

    int j0 = nq * 4, j1 = 64 + nq * 4;
    float bv[8];
    #pragma unroll
    for (int q = 0; q < 4; q++){ bv[q] = bi[j0+q] + bh[j0+q]; bv[4+q] = bi[j1+q] + bh[j1+q]; }

    float* base = g_xp + ((size_t)(d * 64 + b) * 1024 + s0) * 128;
    #pragma unroll
    for (int b4 = 0; b4 < 4; b4++){
        float* dst = base + (size_t)(bq * 4 + b4) * 128;
        float2 v0 = unpk(acc[b4][0]); v0.x += bv[0]; v0.y += bv[1];
        float2 v1 = unpk(acc[b4][1]); v1.x += bv[2]; v1.y += bv[3];
        float2 v2 = unpk(acc[b4][2]); v2.x += bv[4]; v2.y += bv[5];
        float2 v3 = unpk(acc[b4][3]); v3.x += bv[6]; v3.y += bv[7];
        *(float2*)(dst + j0)     = v0;
        *(float2*)(dst + j0 + 2) = v1;
        *(float2*)(dst + j1)     = v2;
        *(float2*)(dst + j1 + 2) = v3;
    }
}

// ---------------- xproj layer 1: tiled GEMM, K=64 ----------------
__global__ void __launch_bounds__(256) xproj1_kernel(
    const float* __restrict__ wf, const float* __restrict__ bif, const float* __restrict__ bhf,
    const float* __restrict__ wr, const float* __restrict__ bir, const float* __restrict__ bhr)
{
    __shared__ float ws[32 * TW];
    __shared__ float fs[32 * TW];
    const int tid = threadIdx.x;
    const int s0 = blockIdx.x * 64;
    const int b  = blockIdx.y;
    const int d  = blockIdx.z;
    const float* w  = d ? wr : wf;
    const float* bi = d ? bir : bif;
    const float* bh = d ? bhr : bhf;

    const int sn  = tid & 127, skq = tid >> 7;
    const int xr  = tid & 63,  xkq = tid >> 6;
    int s = s0 + xr;
    int tsrc = d ? (1023 - s) : s;
    const float* wptr = w + sn * 64 + skq * 16;
    const float* hptr = g_h0 + ((size_t)b * 1024 + tsrc) * 64 + xkq * 8;

    const int nq = tid & 15;
    const int bq = tid >> 4;
    U64 acc[4][4];
    #pragma unroll
    for (int i = 0; i < 4; i++)
        #pragma unroll
        for (int j = 0; j < 4; j++) acc[i][j] = 0ull;

    #pragma unroll
    for (int ch = 0; ch < 2; ch++){
        if (ch){ __syncthreads(); }
        {
            const float4* src = (const float4*)(wptr + ch * 32);
            float4 v0 = src[0], v1 = src[1], v2 = src[2], v3 = src[3];
            int kb = skq * 16;
            ws[(kb+ 0)*TW + sn] = v0.x; ws[(kb+ 1)*TW + sn] = v0.y;
            ws[(kb+ 2)*TW + sn] = v0.z; ws[(kb+ 3)*TW + sn] = v0.w;
            ws[(kb+ 4)*TW + sn] = v1.x; ws[(kb+ 5)*TW + sn] = v1.y;
            ws[(kb+ 6)*TW + sn] = v1.z; ws[(kb+ 7)*TW + sn] = v1.w;
            ws[(kb+ 8)*TW + sn] = v2.x; ws[(kb+ 9)*TW + sn] = v2.y;
            ws[(kb+10)*TW + sn] = v2.z; ws[(kb+11)*TW + sn] = v2.w;
            ws[(kb+12)*TW + sn] = v3.x; ws[(kb+13)*TW + sn] = v3.y;
            ws[(kb+14)*TW + sn] = v3.z; ws[(kb+15)*TW + sn] = v3.w;
        }
        {
            const float4* src = (const float4*)(hptr + ch * 32);
            float4 u0 = src[0], u1 = src[1];
            int kb = xkq * 8;
            *(float2*)&fs[(kb+0)*TW + 2*xr] = make_float2(u0.x, u0.x);
            *(float2*)&fs[(kb+1)*TW + 2*xr] = make_float2(u0.y, u0.y);
            *(float2*)&fs[(kb+2)*TW + 2*xr] = make_float2(u0.z, u0.z);
            *(float2*)&fs[(kb+3)*TW + 2*xr] = make_float2(u0.w, u0.w);
            *(float2*)&fs[(kb+4)*TW + 2*xr] = make_float2(u1.x, u1.x);
            *(float2*)&fs[(kb+5)*TW + 2*xr] = make_float2(u1.y, u1.y);
            *(float2*)&fs[(kb+6)*TW + 2*xr] = make_float2(u1.z, u1.z);
            *(float2*)&fs[(kb+7)*TW + 2*xr] = make_float2(u1.w, u1.w);
        }
        __syncthreads();
        #pragma unroll
        for (int kk = 0; kk < 32; kk++){
            ulonglong2 wa = *(const ulonglong2*)&ws[kk*TW + nq*4];
            ulonglong2 wb = *(const ulonglong2*)&ws[kk*TW + 64 + nq*4];
            ulonglong2 xa = *(const ulonglong2*)&fs[kk*TW + bq*8];
            ulonglong2 xc = *(const ulonglong2*)&fs[kk*TW + bq*8 + 4];
            U64 xv0 = xa.x, xv1 = xa.y, xv2 = xc.x, xv3 = xc.y;
            ffma2(acc[0][0], xv0, wa.x); ffma2(acc[0][1], xv0, wa.y);
            ffma2(acc[0][2], xv0, wb.x); ffma2(acc[0][3], xv0, wb.y);
            ffma2(acc[1][0], xv1, wa.x); ffma2(acc[1][1], xv1, wa.y);
            ffma2(acc[1][2], xv1, wb.x); ffma2(acc[1][3], xv1, wb.y);
            ffma2(acc[2][0], xv2, wa.x); ffma2(acc[2][1], xv2, wa.y);
            ffma2(acc[2][2], xv2, wb.x); ffma2(acc[2][3], xv2, wb.y);
            ffma2(acc[3][0], xv3, wa.x); ffma2(acc[3][1], xv3, wa.y);
            ffma2(acc[3][2], xv3, wb.x); ffma2(acc[3][3], xv3, wb.y);
        }
    }

    int j0 = nq * 4, j1 = 64 + nq * 4;
    float bv[8];
    #pragma unroll
    for (int q = 0; q < 4; q++){ bv[q] = bi[j0+q] + bh[j0+q]; bv[4+q] = bi[j1+q] + bh[j1+q]; }

    float* base = g_xp + ((size_t)(d * 64 + b) * 1024 + s0) * 128;
    #pragma unroll
    for (int b4 = 0; b4 < 4; b4++){
        float* dst = base + (size_t)(bq * 4 + b4) * 128;
        float2 v0 = unpk(acc[b4][0]); v0.x += bv[0]; v0.y += bv[1];
        float2 v1 = unpk(acc[b4][1]); v1.x += bv[2]; v1.y += bv[3];
        float2 v2 = unpk(acc[b4][2]); v2.x += bv[4]; v2.y += bv[5];
        float2 v3 = unpk(acc[b4][3]); v3.x += bv[6]; v3.y += bv[7];
        *(float2*)(dst + j0)     = v0;
        *(float2*)(dst + j0 + 2) = v1;
        *(float2*)(dst + j1)     = v2;
        *(float2*)(dst + j1 + 2) = v3;
    }
}

// ---------------- LSTM: 4 warps/(dir,batch), one barrier/step (unchanged) ----------------
__global__ void __launch_bounds__(128, 1) lstm_kernel(
    const float* __restrict__ whh_f, const float* __restrict__ whh_r, int outsel)
{
    const int blk = blockIdx.x;
    const int d = blk >> 6, b = blk & 63;
    const int tid = threadIdx.x;
    const int g = tid >> 5;
    const int hh = tid & 31;
    float* hout = outsel ? g_h1 : g_h0;
    const float* whh = d ? whh_r : whh_f;

    U64 wp[16];
    {
        const ulonglong2* wr2 = (const ulonglong2*)(whh + (g * 32 + hh) * 32);
        #pragma unroll
        for (int r = 0; r < 8; r++){ ulonglong2 v = wr2[r]; wp[2*r] = v.x; wp[2*r+1] = v.y; }
    }

    __shared__ __align__(16) float hs[32];
    __shared__ __align__(16) float gbuf[2][128];
    if (tid < 32) hs[tid] = 0.0f;
    float c = 0.0f;
    __syncthreads();

    const float* xq = g_xp + (size_t)(d * 64 + b) * 1024 * 128 + g * 32 + hh;
    float cur = xq[0];
    float nxt = xq[128];

    float* outp = hout + (size_t)b * 1024 * 64 + d * 32 + hh;

    for (int s = 0; s < 1024; s++){
        float nn = 0.0f;
        if (s + 2 < 1024) nn = xq[(size_t)(s + 2) * 128];

        U64 a0 = 0ull, a1 = 0ull;
        const ulonglong2* h2 = (const ulonglong2*)hs;
        #pragma unroll
        for (int r = 0; r < 8; r++){
            ulonglong2 hv = h2[r];
            ffma2(a0, hv.x, wp[2*r]);
            ffma2(a1, hv.y, wp[2*r+1]);
        }
        float pre = cur + sum2(add2(a0, a1));
        float act = (g == 2) ? tanhx(pre) : sigf(pre);
        float* gb = gbuf[s & 1];
        gb[g * 32 + hh] = act;
        __syncthreads();

        float iv = gb[hh];
        float fv = gb[32 + hh];
        float gv = gb[64 + hh];
        float ov = gb[96 + hh];
        c = fmaf(fv, c, iv * gv);
        float hval = ov * tanhx(c);
        hs[hh] = hval;
        __syncwarp();
        if (g == 0){
            int tout = d ? (1023 - s) : s;
            outp[(size_t)tout * 64] = hval;
        }
        cur = nxt; nxt = nn;
    }
}

// ---------------- fc GEMM v2: 16n x 8b thread tile, packed-X, smem-lean ----------------
// part[split][64][N] = X[64][K] @ W[N][K]^T. Block: 128 thr, tile 256n x 64b.
#define WS2 264   // W smem row stride (256 + 8 pad), 16B aligned
#define FS2 68    // X smem row stride (64 + 4 pad), 16B aligned

__global__ void __launch_bounds__(128) fc_kernel(
    const float* __restrict__ W, int sel, int N, int K, int kPerSplit)
{
    const float* __restrict__ X = sel ? g_hidden : g_h1;
    float* __restrict__ part = sel ? g_part2 : g_part1;

    __shared__ float ws[2][16 * WS2];  // [k][n]
    __shared__ float fs[2][16 * FS2];  // [k][b]

    const int tid = threadIdx.x;
    const int nh = tid & 15;          // 16 consecutive n at nbase + nh*16
    const int bg = tid >> 4;          // 8 consecutive b at bg*8
    const int nbase = blockIdx.x * 256;
    const int kstart = blockIdx.y * kPerSplit;

    const float* wptrA = W + (size_t)(nbase + tid) * K + kstart;
    const float* wptrB = W + (size_t)(nbase + tid + 128) * K + kstart;
    const float* xptr  = X + (size_t)(tid & 63) * K + kstart + (tid >> 6) * 8;
    const int xkb = (tid >> 6) * 8;
    const int xb  = tid & 63;

    U64 acc[8][8];   // [bb][np] : 8 b x 8 n-pairs (16 n)
    #pragma unroll
    for (int i = 0; i < 8; i++)
        #pragma unroll
        for (int j = 0; j < 8; j++) acc[i][j] = 0ull;

    // prefetch chunk 0 into registers
    float4 wa0, wa1, wa2, wa3, wb0, wb1, wb2, wb3, xr0, xr1;
    {
        const float4* sA = (const float4*)wptrA;
        wa0 = sA[0]; wa1 = sA[1]; wa2 = sA[2]; wa3 = sA[3];
        const float4* sB = (const float4*)wptrB;
        wb0 = sB[0]; wb1 = sB[1]; wb2 = sB[2]; wb3 = sB[3];
        const float4* sX = (const float4*)xptr;
        xr0 = sX[0]; xr1 = sX[1];
    }

    const int nchunk = kPerSplit / 16;
    for (int ch = 0; ch < nchunk; ch++){
        const int buf = ch & 1;
        {   // stage regs -> smem (transposed, conflict-free 128B warp spans)
            float* wsb = ws[buf];
            wsb[ 0*WS2 + tid] = wa0.x; wsb[ 1*WS2 + tid] = wa0.y;
            wsb[ 2*WS2 + tid] = wa0.z; wsb[ 3*WS2 + tid] = wa0.w;
            wsb[ 4*WS2 + tid] = wa1.x; wsb[ 5*WS2 + tid] = wa1.y;
            wsb[ 6*WS2 + tid] = wa1.z; wsb[ 7*WS2 + tid] = wa1.w;
            wsb[ 8*WS2 + tid] = wa2.x; wsb[ 9*WS2 + tid] = wa2.y;
            wsb[10*WS2 + tid] = wa2.z; wsb[11*WS2 + tid] = wa2.w;
            wsb[12*WS2 + tid] = wa3.x; wsb[13*WS2 + tid] = wa3.y;
            wsb[14*WS2 + tid] = wa3.z; wsb[15*WS2 + tid] = wa3.w;
            float* wsb2 = wsb + 128 + tid;
            wsb2[ 0*WS2] = wb0.x; wsb2[ 1*WS2] = wb0.y;
            wsb2[ 2*WS2] = wb0.z; wsb2[ 3*WS2] = wb0.w;
            wsb2[ 4*WS2] = wb1.x; wsb2[ 5*WS2] = wb1.y;
            wsb2[ 6*WS2] = wb1.z; wsb2[ 7*WS2] = wb1.w;
            wsb2[ 8*WS2] = wb2.x; wsb2[ 9*WS2] = wb2.y;
            wsb2[10*WS2] = wb2.z; wsb2[11*WS2] = wb2.w;
            wsb2[12*WS2] = wb3.x; wsb2[13*WS2] = wb3.y;
            wsb2[14*WS2] = wb3.z; wsb2[15*WS2] = wb3.w;
            float* fsb = fs[buf];
            fsb[(xkb+0)*FS2 + xb] = xr0.x; fsb[(xkb+1)*FS2 + xb] = xr0.y;
            fsb[(xkb+2)*FS2 + xb] = xr0.z; fsb[(xkb+3)*FS2 + xb] = xr0.w;
            fsb[(xkb+4)*FS2 + xb] = xr1.x; fsb[(xkb+5)*FS2 + xb] = xr1.y;
            fsb[(xkb+6)*FS2 + xb] = xr1.z; fsb[(xkb+7)*FS2 + xb] = xr1.w;
        }
        __syncthreads();
        if (ch + 1 < nchunk){   // global prefetch for next chunk
            const float4* sA = (const float4*)(wptrA + (ch + 1) * 16);
            wa0 = sA[0]; wa1 = sA[1]; wa2 = sA[2]; wa3 = sA[3];
            const float4* sB = (const float4*)(wptrB + (ch + 1) * 16);
            wb0 = sB[0]; wb1 = sB[1]; wb2 = sB[2]; wb3 = sB[3];
            const float4* sX = (const float4*)(xptr + (ch + 1) * 16);
            xr0 = sX[0]; xr1 = sX[1];
        }
        const float* wsb = ws[buf];
        const float* fsb = fs[buf];
        #pragma unroll
        for (int kk = 0; kk < 16; kk++){
            const float* wrow = wsb + kk * WS2 + nh * 16;
            ulonglong2 w01 = *(const ulonglong2*)(wrow);
            ulonglong2 w23 = *(const ulonglong2*)(wrow + 4);
            ulonglong2 w45 = *(const ulonglong2*)(wrow + 8);
            ulonglong2 w67 = *(const ulonglong2*)(wrow + 12);
            const float* xrow = fsb + kk * FS2 + bg * 8;
            float4 x03 = *(const float4*)(xrow);
            float4 x47 = *(const float4*)(xrow + 4);
            U64 wv[8] = {w01.x, w01.y, w23.x, w23.y, w45.x, w45.y, w67.x, w67.y};
            U64 xd[8];
            xd[0] = pack2(x03.x, x03.x); xd[1] = pack2(x03.y, x03.y);
            xd[2] = pack2(x03.z, x03.z); xd[3] = pack2(x03.w, x03.w);
            xd[4] = pack2(x47.x, x47.x); xd[5] = pack2(x47.y, x47.y);
            xd[6] = pack2(x47.z, x47.z); xd[7] = pack2(x47.w, x47.w);
            #pragma unroll
            for (int bb = 0; bb < 8; bb++)
                #pragma unroll
                for (int np = 0; np < 8; np++)
                    ffma2(acc[bb][np], xd[bb], wv[np]);
        }
        __syncthreads();
    }

    #pragma unroll
    for (int bb = 0; bb < 8; bb++){
        int b = bg * 8 + bb;
        float* dst = part + ((size_t)blockIdx.y * 64 + b) * N + nbase + nh * 16;
        ulonglong2 s0, s1, s2, s3;
        s0.x = acc[bb][0]; s0.y = acc[bb][1];
        s1.x = acc[bb][2]; s1.y = acc[bb][3];
        s2.x = acc[bb][4]; s2.y = acc[bb][5];
        s3.x = acc[bb][6]; s3.y = acc[bb][7];
        *(ulonglong2*)(dst)      = s0;
        *(ulonglong2*)(dst + 4)  = s1;
        *(ulonglong2*)(dst + 8)  = s2;
        *(ulonglong2*)(dst + 12) = s3;
    }
}

// ---------------- split-K reductions ----------------
__global__ void reduce1_kernel(const float* __restrict__ bias){
    int i = blockIdx.x * 256 + threadIdx.x;   // 131072
    int m = i & 2047, b = i >> 11;
    float acc = bias[m];
    #pragma unroll
    for (int s = 0; s < 64; s++) acc += g_part1[((size_t)s * 64 + b) * 2048 + m];
    g_hidden[i] = fmaxf(acc, 0.0f);
}

__global__ void reduce2_kernel(const float* __restrict__ bias, float* __restrict__ out){
    int i = blockIdx.x * 256 + threadIdx.x;   // 589824
    int n = i % 9216, b = i / 9216;
    float acc = bias[n];
    #pragma unroll
    for (int s = 0; s < 4; s++) acc += g_part2[((size_t)s * 64 + b) * 9216 + n];
    out[i] = acc;
}

// ---------------- launcher ----------------
extern "C" void kernel_launch(void* const* d_in, const int* in_sizes, int n_in,
                              void* d_out, int out_size)
{
    const float* x     = (const float*)d_in[0];
    const float* wih0  = (const float*)d_in[1];
    const float* whh0  = (const float*)d_in[2];
    const float* bih0  = (const float*)d_in[3];
    const float* bhh0  = (const float*)d_in[4];
    const float* wih0r = (const float*)d_in[5];
    const float* whh0r = (const float*)d_in[6];
    const float* bih0r = (const float*)d_in[7];
    const float* bhh0r = (const float*)d_in[8];
    const float* wih1  = (const float*)d_in[9];
    const float* whh1  = (const float*)d_in[10];
    const float* bih1  = (const float*)d_in[11];
    const float* bhh1  = (const float*)d_in[12];
    const float* wih1r = (const float*)d_in[13];
    const float* whh1r = (const float*)d_in[14];
    const float* bih1r = (const float*)d_in[15];
    const float* bhh1r = (const float*)d_in[16];
    const float* fc1w  = (const float*)d_in[17];
    const float* fc1b  = (const float*)d_in[18];
    const float* fc2w  = (const float*)d_in[19];
    const float* fc2b  = (const float*)d_in[20];
    float* out = (float*)d_out;

    xproj0_kernel<<<dim3(16, 64, 2), 256>>>(x, wih0, bih0, bhh0, wih0r, bih0r, bhh0r);
    lstm_kernel<<<128, 128>>>(whh0, whh0r, 0);
    xproj1_kernel<<<dim3(16, 64, 2), 256>>>(wih1, bih1, bhh1, wih1r, bih1r, bhh1r);
    lstm_kernel<<<128, 128>>>(whh1, whh1r, 1);

    // fc1: N=2048 (8 n-blocks), K=65536, split-K=64 (kPerSplit=1024) -> grid (8, 64)
    fc_kernel<<<dim3(8, 64), 128>>>(fc1w, 0, 2048, 65536, 1024);
    reduce1_kernel<<<512, 256>>>(fc1b);

    // fc2: N=9216 (36 n-blocks), K=2048, split-K=4 (kPerSplit=512) -> grid (36, 4)
    fc_kernel<<<dim3(36, 4), 128>>>(fc2w, 1, 9216, 2048, 512);
    reduce2_kernel<<<2304, 256>>>(fc2b, out);
}

// round 9
// speedup vs baseline: 1.1533x; 1.1533x over previous
#include <cuda_runtime.h>

typedef unsigned long long U64;

// ---------------- static device scratch ----------------
__device__ float g_xp[16777216];   // [2][64][1024][128] gate pre-activations
__device__ float g_h0[4194304];    // [64][1024][64]
__device__ float g_h1[4194304];    // [64][1024][64]
__device__ float g_part1[8388608]; // [64][64][2048] fc1 split-K partials
__device__ float g_hidden[131072]; // [64][2048]
__device__ float g_part2[2359296]; // [4][64][9216] fc2 split-K partials

// ---------------- helpers ----------------
__device__ __forceinline__ void ffma2(U64 &acc, U64 a, U64 b){
    asm("fma.rn.f32x2 %0, %1, %2, %0;" : "+l"(acc) : "l"(a), "l"(b));
}
__device__ __forceinline__ U64 add2(U64 a, U64 b){
    U64 r; asm("add.rn.f32x2 %0, %1, %2;" : "=l"(r) : "l"(a), "l"(b)); return r;
}
__device__ __forceinline__ float2 unpk(U64 v){
    float2 r; asm("mov.b64 {%0, %1}, %2;" : "=f"(r.x), "=f"(r.y) : "l"(v)); return r;
}
__device__ __forceinline__ U64 pack2(float lo, float hi){
    U64 r; asm("mov.b64 %0, {%1, %2};" : "=l"(r) : "f"(lo), "f"(hi)); return r;
}
__device__ __forceinline__ float sum2(U64 v){ float2 r = unpk(v); return r.x + r.y; }
__device__ __forceinline__ float fex2(float x){ float r; asm("ex2.approx.ftz.f32 %0, %1;" : "=f"(r) : "f"(x)); return r; }
__device__ __forceinline__ float frcp(float x){ float r; asm("rcp.approx.ftz.f32 %0, %1;" : "=f"(r) : "f"(x)); return r; }
__device__ __forceinline__ float sigf (float x){ return frcp(1.0f + fex2(-1.4426950408889634f * x)); }
__device__ __forceinline__ float tanhx(float x){ return fmaf(-2.0f, frcp(1.0f + fex2(2.8853900817779268f * x)), 1.0f); }

#define TW 132   // padded smem row stride (floats) for xproj kernels

// ---------------- xproj layer 0: tiled, K=9 ----------------
__global__ void __launch_bounds__(256) xproj0_kernel(const float* __restrict__ x,
    const float* __restrict__ wf, const float* __restrict__ bif, const float* __restrict__ bhf,
    const float* __restrict__ wr, const float* __restrict__ bir, const float* __restrict__ bhr)
{
    __shared__ float ws[9 * TW];
    __shared__ float fs[9 * TW];
    const int tid = threadIdx.x;
    const int s0 = blockIdx.x * 64;
    const int b  = blockIdx.y;
    const int d  = blockIdx.z;
    const float* w  = d ? wr : wf;
    const float* bi = d ? bir : bif;
    const float* bh = d ? bhr : bhf;

    if (tid < 128){
        const float* src = w + tid * 9;
        #pragma unroll
        for (int k = 0; k < 9; k++) ws[k * TW + tid] = src[k];
    } else if (tid < 192){
        int r = tid - 128;
        int s = s0 + r;
        int tsrc = d ? (1023 - s) : s;
        const float* src = x + ((size_t)b * 1024 + tsrc) * 9;
        #pragma unroll
        for (int k = 0; k < 9; k++){
            float v = src[k];
            *(float2*)&fs[k * TW + 2 * r] = make_float2(v, v);
        }
    }
    __syncthreads();

    const int nq = tid & 15;
    const int bq = tid >> 4;
    U64 acc[4][4];
    #pragma unroll
    for (int i = 0; i < 4; i++)
        #pragma unroll
        for (int j = 0; j < 4; j++) acc[i][j] = 0ull;

    #pragma unroll
    for (int kk = 0; kk < 9; kk++){
        ulonglong2 wa = *(const ulonglong2*)&ws[kk*TW + nq*4];
        ulonglong2 wb = *(const ulonglong2*)&ws[kk*TW + 64 + nq*4];
        ulonglong2 xa = *(const ulonglong2*)&fs[kk*TW + bq*8];
        ulonglong2 xc = *(const ulonglong2*)&fs[kk*TW + bq*8 + 4];
        U64 xv0 = xa.x, xv1 = xa.y, xv2 = xc.x, xv3 = xc.y;
        ffma2(acc[0][0], xv0, wa.x); ffma2(acc[0][1], xv0, wa.y);
        ffma2(acc[0][2], xv0, wb.x); ffma2(acc[0][3], xv0, wb.y);
        ffma2(acc[1][0], xv1, wa.x); ffma2(acc[1][1], xv1, wa.y);
        ffma2(acc[1][2], xv1, wb.x); ffma2(acc[1][3], xv1, wb.y);
        ffma2(acc[2][0], xv2, wa.x); ffma2(acc[2][1], xv2, wa.y);
        ffma2(acc[2][2], xv2, wb.x); ffma2(acc[2][3], xv2, wb.y);
        ffma2(acc[3][0], xv3, wa.x); ffma2(acc[3][1], xv3, wa.y);
        ffma2(acc[3][2], xv3, wb.x); ffma2(acc[3][3], xv3, wb.y);
    }

    int j0 = nq * 4, j1 = 64 + nq * 4;
    float bv[8];
    #pragma unroll
    for (int q = 0; q < 4; q++){ bv[q] = bi[j0+q] + bh[j0+q]; bv[4+q] = bi[j1+q] + bh[j1+q]; }

    float* base = g_xp + ((size_t)(d * 64 + b) * 1024 + s0) * 128;
    #pragma unroll
    for (int b4 = 0; b4 < 4; b4++){
        float* dst = base + (size_t)(bq * 4 + b4) * 128;
        float2 v0 = unpk(acc[b4][0]); v0.x += bv[0]; v0.y += bv[1];
        float2 v1 = unpk(acc[b4][1]); v1.x += bv[2]; v1.y += bv[3];
        float2 v2 = unpk(acc[b4][2]); v2.x += bv[4]; v2.y += bv[5];
        float2 v3 = unpk(acc[b4][3]); v3.x += bv[6]; v3.y += bv[7];
        *(float2*)(dst + j0)     = v0;
        *(float2*)(dst + j0 + 2) = v1;
        *(float2*)(dst + j1)     = v2;
        *(float2*)(dst + j1 + 2) = v3;
    }
}

// ---------------- xproj layer 1: tiled GEMM, K=64 ----------------
__global__ void __launch_bounds__(256) xproj1_kernel(
    const float* __restrict__ wf, const float* __restrict__ bif, const float* __restrict__ bhf,
    const float* __restrict__ wr, const float* __restrict__ bir, const float* __restrict__ bhr)
{
    __shared__ float ws[32 * TW];
    __shared__ float fs[32 * TW];
    const int tid = threadIdx.x;
    const int s0 = blockIdx.x * 64;
    const int b  = blockIdx.y;
    const int d  = blockIdx.z;
    const float* w  = d ? wr : wf;
    const float* bi = d ? bir : bif;
    const float* bh = d ? bhr : bhf;

    const int sn  = tid & 127, skq = tid >> 7;
    const int xr  = tid & 63,  xkq = tid >> 6;
    int s = s0 + xr;
    int tsrc = d ? (1023 - s) : s;
    const float* wptr = w + sn * 64 + skq * 16;
    const float* hptr = g_h0 + ((size_t)b * 1024 + tsrc) * 64 + xkq * 8;

    const int nq = tid & 15;
    const int bq = tid >> 4;
    U64 acc[4][4];
    #pragma unroll
    for (int i = 0; i < 4; i++)
        #pragma unroll
        for (int j = 0; j < 4; j++) acc[i][j] = 0ull;

    #pragma unroll
    for (int ch = 0; ch < 2; ch++){
        if (ch){ __syncthreads(); }
        {
            const float4* src = (const float4*)(wptr + ch * 32);
            float4 v0 = src[0], v1 = src[1], v2 = src[2], v3 = src[3];
            int kb = skq * 16;
            ws[(kb+ 0)*TW + sn] = v0.x; ws[(kb+ 1)*TW + sn] = v0.y;
            ws[(kb+ 2)*TW + sn] = v0.z; ws[(kb+ 3)*TW + sn] = v0.w;
            ws[(kb+ 4)*TW + sn] = v1.x; ws[(kb+ 5)*TW + sn] = v1.y;
            ws[(kb+ 6)*TW + sn] = v1.z; ws[(kb+ 7)*TW + sn] = v1.w;
            ws[(kb+ 8)*TW + sn] = v2.x; ws[(kb+ 9)*TW + sn] = v2.y;
            ws[(kb+10)*TW + sn] = v2.z; ws[(kb+11)*TW + sn] = v2.w;
            ws[(kb+12)*TW + sn] = v3.x; ws[(kb+13)*TW + sn] = v3.y;
            ws[(kb+14)*TW + sn] = v3.z; ws[(kb+15)*TW + sn] = v3.w;
        }
        {
            const float4* src = (const float4*)(hptr + ch * 32);
            float4 u0 = src[0], u1 = src[1];
            int kb = xkq * 8;
            *(float2*)&fs[(kb+0)*TW + 2*xr] = make_float2(u0.x, u0.x);
            *(float2*)&fs[(kb+1)*TW + 2*xr] = make_float2(u0.y, u0.y);
            *(float2*)&fs[(kb+2)*TW + 2*xr] = make_float2(u0.z, u0.z);
            *(float2*)&fs[(kb+3)*TW + 2*xr] = make_float2(u0.w, u0.w);
            *(float2*)&fs[(kb+4)*TW + 2*xr] = make_float2(u1.x, u1.x);
            *(float2*)&fs[(kb+5)*TW + 2*xr] = make_float2(u1.y, u1.y);
            *(float2*)&fs[(kb+6)*TW + 2*xr] = make_float2(u1.z, u1.z);
            *(float2*)&fs[(kb+7)*TW + 2*xr] = make_float2(u1.w, u1.w);
        }
        __syncthreads();
        #pragma unroll
        for (int kk = 0; kk < 32; kk++){
            ulonglong2 wa = *(const ulonglong2*)&ws[kk*TW + nq*4];
            ulonglong2 wb = *(const ulonglong2*)&ws[kk*TW + 64 + nq*4];
            ulonglong2 xa = *(const ulonglong2*)&fs[kk*TW + bq*8];
            ulonglong2 xc = *(const ulonglong2*)&fs[kk*TW + bq*8 + 4];
            U64 xv0 = xa.x, xv1 = xa.y, xv2 = xc.x, xv3 = xc.y;
            ffma2(acc[0][0], xv0, wa.x); ffma2(acc[0][1], xv0, wa.y);
            ffma2(acc[0][2], xv0, wb.x); ffma2(acc[0][3], xv0, wb.y);
            ffma2(acc[1][0], xv1, wa.x); ffma2(acc[1][1], xv1, wa.y);
            ffma2(acc[1][2], xv1, wb.x); ffma2(acc[1][3], xv1, wb.y);
            ffma2(acc[2][0], xv2, wa.x); ffma2(acc[2][1], xv2, wa.y);
            ffma2(acc[2][2], xv2, wb.x); ffma2(acc[2][3], xv2, wb.y);
            ffma2(acc[3][0], xv3, wa.x); ffma2(acc[3][1], xv3, wa.y);
            ffma2(acc[3][2], xv3, wb.x); ffma2(acc[3][3], xv3, wb.y);
        }
    }

    int j0 = nq * 4, j1 = 64 + nq * 4;
    float bv[8];
    #pragma unroll
    for (int q = 0; q < 4; q++){ bv[q] = bi[j0+q] + bh[j0+q]; bv[4+q] = bi[j1+q] + bh[j1+q]; }

    float* base = g_xp + ((size_t)(d * 64 + b) * 1024 + s0) * 128;
    #pragma unroll
    for (int b4 = 0; b4 < 4; b4++){
        float* dst = base + (size_t)(bq * 4 + b4) * 128;
        float2 v0 = unpk(acc[b4][0]); v0.x += bv[0]; v0.y += bv[1];
        float2 v1 = unpk(acc[b4][1]); v1.x += bv[2]; v1.y += bv[3];
        float2 v2 = unpk(acc[b4][2]); v2.x += bv[4]; v2.y += bv[5];
        float2 v3 = unpk(acc[b4][3]); v3.x += bv[6]; v3.y += bv[7];
        *(float2*)(dst + j0)     = v0;
        *(float2*)(dst + j0 + 2) = v1;
        *(float2*)(dst + j1)     = v2;
        *(float2*)(dst + j1 + 2) = v3;
    }
}

// ---------------- LSTM: 4 warps/(dir,batch), one barrier/step (unchanged) ----------------
__global__ void __launch_bounds__(128, 1) lstm_kernel(
    const float* __restrict__ whh_f, const float* __restrict__ whh_r, int outsel)
{
    const int blk = blockIdx.x;
    const int d = blk >> 6, b = blk & 63;
    const int tid = threadIdx.x;
    const int g = tid >> 5;
    const int hh = tid & 31;
    float* hout = outsel ? g_h1 : g_h0;
    const float* whh = d ? whh_r : whh_f;

    U64 wp[16];
    {
        const ulonglong2* wr2 = (const ulonglong2*)(whh + (g * 32 + hh) * 32);
        #pragma unroll
        for (int r = 0; r < 8; r++){ ulonglong2 v = wr2[r]; wp[2*r] = v.x; wp[2*r+1] = v.y; }
    }

    __shared__ __align__(16) float hs[32];
    __shared__ __align__(16) float gbuf[2][128];
    if (tid < 32) hs[tid] = 0.0f;
    float c = 0.0f;
    __syncthreads();

    const float* xq = g_xp + (size_t)(d * 64 + b) * 1024 * 128 + g * 32 + hh;
    float cur = xq[0];
    float nxt = xq[128];

    float* outp = hout + (size_t)b * 1024 * 64 + d * 32 + hh;

    for (int s = 0; s < 1024; s++){
        float nn = 0.0f;
        if (s + 2 < 1024) nn = xq[(size_t)(s + 2) * 128];

        U64 a0 = 0ull, a1 = 0ull;
        const ulonglong2* h2 = (const ulonglong2*)hs;
        #pragma unroll
        for (int r = 0; r < 8; r++){
            ulonglong2 hv = h2[r];
            ffma2(a0, hv.x, wp[2*r]);
            ffma2(a1, hv.y, wp[2*r+1]);
        }
        float pre = cur + sum2(add2(a0, a1));
        float act = (g == 2) ? tanhx(pre) : sigf(pre);
        float* gb = gbuf[s & 1];
        gb[g * 32 + hh] = act;
        __syncthreads();

        float iv = gb[hh];
        float fv = gb[32 + hh];
        float gv = gb[64 + hh];
        float ov = gb[96 + hh];
        c = fmaf(fv, c, iv * gv);
        float hval = ov * tanhx(c);
        hs[hh] = hval;
        __syncwarp();
        if (g == 0){
            int tout = d ? (1023 - s) : s;
            outp[(size_t)tout * 64] = hval;
        }
        cur = nxt; nxt = nn;
    }
}

// ---------------- fc GEMM v3: 256 thr, tile 64b x 256n, thread tile 8b x 8n ----------------
// part[split][64][N] = X[64][K] @ W[N][K]^T
#define WS3 264   // W smem row stride (256 + 8 pad)
#define FS3 68    // X smem row stride (64 + 4 pad)

__global__ void __launch_bounds__(256) fc_kernel(
    const float* __restrict__ W, int sel, int N, int K, int kPerSplit)
{
    const float* __restrict__ X = sel ? g_hidden : g_h1;
    float* __restrict__ part = sel ? g_part2 : g_part1;

    __shared__ float ws[2][16 * WS3];  // [k][n]  33.8KB
    __shared__ float fs[2][16 * FS3];  // [k][b]   8.7KB

    const int tid = threadIdx.x;
    const int nq = tid & 31;          // n-offset nq*8 within 256-wide tile
    const int bq = tid >> 5;          // warp id = b-group of 8 (broadcast X reads)
    const int nbase = blockIdx.x * 256;
    const int kstart = blockIdx.y * kPerSplit;

    // staging maps: W row = tid (256 rows), 16 k; X row = tid&63, k-group = tid>>6
    const float* wptr = W + (size_t)(nbase + tid) * K + kstart;
    const int xb = tid & 63, xkq = tid >> 6;
    const float* xptr = X + (size_t)xb * K + kstart + xkq * 4;

    U64 acc[8][4];   // [bb][np]: 8 b x 4 n-pairs (8 n)
    #pragma unroll
    for (int i = 0; i < 8; i++)
        #pragma unroll
        for (int j = 0; j < 4; j++) acc[i][j] = 0ull;

    // prefetch chunk 0 into registers
    float4 w0, w1, w2, w3, xv;
    {
        const float4* sw = (const float4*)wptr;
        w0 = sw[0]; w1 = sw[1]; w2 = sw[2]; w3 = sw[3];
        xv = *(const float4*)xptr;
    }

    const int nchunk = kPerSplit / 16;
    for (int ch = 0; ch < nchunk; ch++){
        const int buf = ch & 1;
        {   // stage regs -> smem (conflict-free: lanes span consecutive n / b)
            float* wsb = ws[buf];
            wsb[ 0*WS3 + tid] = w0.x; wsb[ 1*WS3 + tid] = w0.y;
            wsb[ 2*WS3 + tid] = w0.z; wsb[ 3*WS3 + tid] = w0.w;
            wsb[ 4*WS3 + tid] = w1.x; wsb[ 5*WS3 + tid] = w1.y;
            wsb[ 6*WS3 + tid] = w1.z; wsb[ 7*WS3 + tid] = w1.w;
            wsb[ 8*WS3 + tid] = w2.x; wsb[ 9*WS3 + tid] = w2.y;
            wsb[10*WS3 + tid] = w2.z; wsb[11*WS3 + tid] = w2.w;
            wsb[12*WS3 + tid] = w3.x; wsb[13*WS3 + tid] = w3.y;
            wsb[14*WS3 + tid] = w3.z; wsb[15*WS3 + tid] = w3.w;
            float* fsb = fs[buf];
            int kb = xkq * 4;
            fsb[(kb+0)*FS3 + xb] = xv.x; fsb[(kb+1)*FS3 + xb] = xv.y;
            fsb[(kb+2)*FS3 + xb] = xv.z; fsb[(kb+3)*FS3 + xb] = xv.w;
        }
        __syncthreads();
        if (ch + 1 < nchunk){   // next chunk's global loads in flight over compute
            const float4* sw = (const float4*)(wptr + (ch + 1) * 16);
            w0 = sw[0]; w1 = sw[1]; w2 = sw[2]; w3 = sw[3];
            xv = *(const float4*)(xptr + (ch + 1) * 16);
        }
        const float* wsb = ws[buf];
        const float* fsb = fs[buf];
        #pragma unroll
        for (int kk = 0; kk < 16; kk++){
            const float* wrow = wsb + kk * WS3 + nq * 8;
            ulonglong2 wA = *(const ulonglong2*)(wrow);       // n pairs 0,1
            ulonglong2 wB = *(const ulonglong2*)(wrow + 4);   // n pairs 2,3
            const float* xrow = fsb + kk * FS3 + bq * 8;      // broadcast within warp
            float4 xa = *(const float4*)(xrow);
            float4 xc = *(const float4*)(xrow + 4);
            U64 xd0 = pack2(xa.x, xa.x), xd1 = pack2(xa.y, xa.y);
            U64 xd2 = pack2(xa.z, xa.z), xd3 = pack2(xa.w, xa.w);
            U64 xd4 = pack2(xc.x, xc.x), xd5 = pack2(xc.y, xc.y);
            U64 xd6 = pack2(xc.z, xc.z), xd7 = pack2(xc.w, xc.w);
            ffma2(acc[0][0], xd0, wA.x); ffma2(acc[0][1], xd0, wA.y);
            ffma2(acc[0][2], xd0, wB.x); ffma2(acc[0][3], xd0, wB.y);
            ffma2(acc[1][0], xd1, wA.x); ffma2(acc[1][1], xd1, wA.y);
            ffma2(acc[1][2], xd1, wB.x); ffma2(acc[1][3], xd1, wB.y);
            ffma2(acc[2][0], xd2, wA.x); ffma2(acc[2][1], xd2, wA.y);
            ffma2(acc[2][2], xd2, wB.x); ffma2(acc[2][3], xd2, wB.y);
            ffma2(acc[3][0], xd3, wA.x); ffma2(acc[3][1], xd3, wA.y);
            ffma2(acc[3][2], xd3, wB.x); ffma2(acc[3][3], xd3, wB.y);
            ffma2(acc[4][0], xd4, wA.x); ffma2(acc[4][1], xd4, wA.y);
            ffma2(acc[4][2], xd4, wB.x); ffma2(acc[4][3], xd4, wB.y);
            ffma2(acc[5][0], xd5, wA.x); ffma2(acc[5][1], xd5, wA.y);
            ffma2(acc[5][2], xd5, wB.x); ffma2(acc[5][3], xd5, wB.y);
            ffma2(acc[6][0], xd6, wA.x); ffma2(acc[6][1], xd6, wA.y);
            ffma2(acc[6][2], xd6, wB.x); ffma2(acc[6][3], xd6, wB.y);
            ffma2(acc[7][0], xd7, wA.x); ffma2(acc[7][1], xd7, wA.y);
            ffma2(acc[7][2], xd7, wB.x); ffma2(acc[7][3], xd7, wB.y);
        }
        __syncthreads();
    }

    #pragma unroll
    for (int bb = 0; bb < 8; bb++){
        int b = bq * 8 + bb;
        float* dst = part + ((size_t)blockIdx.y * 64 + b) * N + nbase + nq * 8;
        ulonglong2 s0, s1;
        s0.x = acc[bb][0]; s0.y = acc[bb][1];
        s1.x = acc[bb][2]; s1.y = acc[bb][3];
        *(ulonglong2*)(dst)     = s0;
        *(ulonglong2*)(dst + 4) = s1;
    }
}

// ---------------- split-K reductions ----------------
__global__ void reduce1_kernel(const float* __restrict__ bias){
    int i = blockIdx.x * 256 + threadIdx.x;   // 131072
    int m = i & 2047, b = i >> 11;
    float acc = bias[m];
    #pragma unroll
    for (int s = 0; s < 64; s++) acc += g_part1[((size_t)s * 64 + b) * 2048 + m];
    g_hidden[i] = fmaxf(acc, 0.0f);
}

__global__ void reduce2_kernel(const float* __restrict__ bias, float* __restrict__ out){
    int i = blockIdx.x * 256 + threadIdx.x;   // 589824
    int n = i % 9216, b = i / 9216;
    float acc = bias[n];
    #pragma unroll
    for (int s = 0; s < 4; s++) acc += g_part2[((size_t)s * 64 + b) * 9216 + n];
    out[i] = acc;
}

// ---------------- launcher ----------------
extern "C" void kernel_launch(void* const* d_in, const int* in_sizes, int n_in,
                              void* d_out, int out_size)
{
    const float* x     = (const float*)d_in[0];
    const float* wih0  = (const float*)d_in[1];
    const float* whh0  = (const float*)d_in[2];
    const float* bih0  = (const float*)d_in[3];
    const float* bhh0  = (const float*)d_in[4];
    const float* wih0r = (const float*)d_in[5];
    const float* whh0r = (const float*)d_in[6];
    const float* bih0r = (const float*)d_in[7];
    const float* bhh0r = (const float*)d_in[8];
    const float* wih1  = (const float*)d_in[9];
    const float* whh1  = (const float*)d_in[10];
    const float* bih1  = (const float*)d_in[11];
    const float* bhh1  = (const float*)d_in[12];
    const float* wih1r = (const float*)d_in[13];
    const float* whh1r = (const float*)d_in[14];
    const float* bih1r = (const float*)d_in[15];
    const float* bhh1r = (const float*)d_in[16];
    const float* fc1w  = (const float*)d_in[17];
    const float* fc1b  = (const float*)d_in[18];
    const float* fc2w  = (const float*)d_in[19];
    const float* fc2b  = (const float*)d_in[20];
    float* out = (float*)d_out;

    xproj0_kernel<<<dim3(16, 64, 2), 256>>>(x, wih0, bih0, bhh0, wih0r, bih0r, bhh0r);
    lstm_kernel<<<128, 128>>>(whh0, whh0r, 0);
    xproj1_kernel<<<dim3(16, 64, 2), 256>>>(wih1, bih1, bhh1, wih1r, bih1r, bhh1r);
    lstm_kernel<<<128, 128>>>(whh1, whh1r, 1);

    // fc1: N=2048 (8 n-blocks of 256), K=65536, split-K=64 (kPerSplit=1024) -> grid (8, 64)
    fc_kernel<<<dim3(8, 64), 256>>>(fc1w, 0, 2048, 65536, 1024);
    reduce1_kernel<<<512, 256>>>(fc1b);

    // fc2: N=9216 (36 n-blocks), K=2048, split-K=4 (kPerSplit=512) -> grid (36, 4)
    fc_kernel<<<dim3(36, 4), 256>>>(fc2w, 1, 9216, 2048, 512);
    reduce2_kernel<<<2304, 256>>>(fc2b, out);
}

// round 11
// speedup vs baseline: 1.7200x; 1.4914x over previous
#include <cuda_runtime.h>
#include <cstdint>

typedef unsigned long long U64;

// ---------------- static device scratch ----------------
__device__ float g_xp[16777216];   // [2][64][1024][128] gate pre-activations
__device__ float g_h0[4194304];    // [64][1024][64]
__device__ float g_h1[4194304];    // [64][1024][64]
__device__ float g_part1[8388608]; // [64][64][2048] fc1 split-K partials
__device__ float g_hidden[131072]; // [64][2048]
__device__ float g_part2[2359296]; // [4][64][9216] fc2 split-K partials

// ---------------- helpers ----------------
__device__ __forceinline__ void ffma2(U64 &acc, U64 a, U64 b){
    asm("fma.rn.f32x2 %0, %1, %2, %0;" : "+l"(acc) : "l"(a), "l"(b));
}
__device__ __forceinline__ U64 add2(U64 a, U64 b){
    U64 r; asm("add.rn.f32x2 %0, %1, %2;" : "=l"(r) : "l"(a), "l"(b)); return r;
}
__device__ __forceinline__ float2 unpk(U64 v){
    float2 r; asm("mov.b64 {%0, %1}, %2;" : "=f"(r.x), "=f"(r.y) : "l"(v)); return r;
}
__device__ __forceinline__ U64 pack2(float lo, float hi){
    U64 r; asm("mov.b64 %0, {%1, %2};" : "=l"(r) : "f"(lo), "f"(hi)); return r;
}
__device__ __forceinline__ float sum2(U64 v){ float2 r = unpk(v); return r.x + r.y; }
__device__ __forceinline__ float fex2(float x){ float r; asm("ex2.approx.ftz.f32 %0, %1;" : "=f"(r) : "f"(x)); return r; }
__device__ __forceinline__ float frcp(float x){ float r; asm("rcp.approx.ftz.f32 %0, %1;" : "=f"(r) : "f"(x)); return r; }
__device__ __forceinline__ float sigf (float x){ return frcp(1.0f + fex2(-1.4426950408889634f * x)); }
__device__ __forceinline__ float tanhx(float x){ return fmaf(-2.0f, frcp(1.0f + fex2(2.8853900817779268f * x)), 1.0f); }

// cvt: word = { hi16: bf16(b), lo16: bf16(a) }
__device__ __forceinline__ uint32_t cvt_bf2(float a, float b){
    uint32_t r; asm("cvt.rn.bf16x2.f32 %0, %1, %2;" : "=r"(r) : "f"(b), "f"(a)); return r;
}
__device__ __forceinline__ uint32_t smem_u32(const void* p){
    uint32_t a; asm("{ .reg .u64 t; cvta.to.shared.u64 t, %1; cvt.u32.u64 %0, t; }" : "=r"(a) : "l"(p));
    return a;
}
__device__ __forceinline__ void ldm4(uint32_t* r, uint32_t addr){
    asm volatile("ldmatrix.sync.aligned.m8n8.x4.shared.b16 {%0,%1,%2,%3}, [%4];"
        : "=r"(r[0]), "=r"(r[1]), "=r"(r[2]), "=r"(r[3]) : "r"(addr));
}
__device__ __forceinline__ void mma_bf(float (&d)[4], const uint32_t* a, uint32_t b0, uint32_t b1){
    asm volatile("mma.sync.aligned.m16n8k16.row.col.f32.bf16.bf16.f32 "
        "{%0,%1,%2,%3}, {%4,%5,%6,%7}, {%8,%9}, {%0,%1,%2,%3};"
        : "+f"(d[0]), "+f"(d[1]), "+f"(d[2]), "+f"(d[3])
        : "r"(a[0]), "r"(a[1]), "r"(a[2]), "r"(a[3]), "r"(b0), "r"(b1));
}
// swizzled byte offset of bf16x2 word (row, kpair) in a [row][32k] bf16 tile (64B rows)
__device__ __forceinline__ int swoff(int row, int kp){
    return row*64 + ((((kp>>2) ^ ((row>>1)&3))<<4) | ((kp&3)<<2));
}

#define TW 132   // padded smem row stride (floats) for xproj kernels

// ---------------- xproj layer 0: tiled, K=9 ----------------
__global__ void __launch_bounds__(256) xproj0_kernel(const float* __restrict__ x,
    const float* __restrict__ wf, const float* __restrict__ bif, const float* __restrict__ bhf,
    const float* __restrict__ wr, const float* __restrict__ bir, const float* __restrict__ bhr)
{
    __shared__ float ws[9 * TW];
    __shared__ float fs[9 * TW];
    const int tid = threadIdx.x;
    const int s0 = blockIdx.x * 64;
    const int b  = blockIdx.y;
    const int d  = blockIdx.z;
    const float* w  = d ? wr : wf;
    const float* bi = d ? bir : bif;
    const float* bh = d ? bhr : bhf;

    if (tid < 128){
        const float* src = w + tid * 9;
        #pragma unroll
        for (int k = 0; k < 9; k++) ws[k * TW + tid] = src[k];
    } else if (tid < 192){
        int r = tid - 128;
        int s = s0 + r;
        int tsrc = d ? (1023 - s) : s;
        const float* src = x + ((size_t)b * 1024 + tsrc) * 9;
        #pragma unroll
        for (int k = 0; k < 9; k++){
            float v = src[k];
            *(float2*)&fs[k * TW + 2 * r] = make_float2(v, v);
        }
    }
    __syncthreads();

    const int nq = tid & 15;
    const int bq = tid >> 4;
    U64 acc[4][4];
    #pragma unroll
    for (int i = 0; i < 4; i++)
        #pragma unroll
        for (int j = 0; j < 4; j++) acc[i][j] = 0ull;

    #pragma unroll
    for (int kk = 0; kk < 9; kk++){
        ulonglong2 wa = *(const ulonglong2*)&ws[kk*TW + nq*4];
        ulonglong2 wb = *(const ulonglong2*)&ws[kk*TW + 64 + nq*4];
        ulonglong2 xa = *(const ulonglong2*)&fs[kk*TW + bq*8];
        ulonglong2 xc = *(const ulonglong2*)&fs[kk*TW + bq*8 + 4];
        U64 xv0 = xa.x, xv1 = xa.y, xv2 = xc.x, xv3 = xc.y;
        ffma2(acc[0][0], xv0, wa.x); ffma2(acc[0][1], xv0, wa.y);
        ffma2(acc[0][2], xv0, wb.x); ffma2(acc[0][3], xv0, wb.y);
        ffma2(acc[1][0], xv1, wa.x); ffma2(acc[1][1], xv1, wa.y);
        ffma2(acc[1][2], xv1, wb.x); ffma2(acc[1][3], xv1, wb.y);
        ffma2(acc[2][0], xv2, wa.x); ffma2(acc[2][1], xv2, wa.y);
        ffma2(acc[2][2], xv2, wb.x); ffma2(acc[2][3], xv2, wb.y);
        ffma2(acc[3][0], xv3, wa.x); ffma2(acc[3][1], xv3, wa.y);
        ffma2(acc[3][2], xv3, wb.x); ffma2(acc[3][3], xv3, wb.y);
    }

    int j0 = nq * 4, j1 = 64 + nq * 4;
    float bv[8];
    #pragma unroll
    for (int q = 0; q < 4; q++){ bv[q] = bi[j0+q] + bh[j0+q]; bv[4+q] = bi[j1+q] + bh[j1+q]; }

    float* base = g_xp + ((size_t)(d * 64 + b) * 1024 + s0) * 128;
    #pragma unroll
    for (int b4 = 0; b4 < 4; b4++){
        float* dst = base + (size_t)(bq * 4 + b4) * 128;
        float2 v0 = unpk(acc[b4][0]); v0.x += bv[0]; v0.y += bv[1];
        float2 v1 = unpk(acc[b4][1]); v1.x += bv[2]; v1.y += bv[3];
        float2 v2 = unpk(acc[b4][2]); v2.x += bv[4]; v2.y += bv[5];
        float2 v3 = unpk(acc[b4][3]); v3.x += bv[6]; v3.y += bv[7];
        *(float2*)(dst + j0)     = v0;
        *(float2*)(dst + j0 + 2) = v1;
        *(float2*)(dst + j1)     = v2;
        *(float2*)(dst + j1 + 2) = v3;
    }
}

// ---------------- xproj layer 1: tiled GEMM, K=64 ----------------
__global__ void __launch_bounds__(256) xproj1_kernel(
    const float* __restrict__ wf, const float* __restrict__ bif, const float* __restrict__ bhf,
    const float* __restrict__ wr, const float* __restrict__ bir, const float* __restrict__ bhr)
{
    __shared__ float ws[32 * TW];
    __shared__ float fs[32 * TW];
    const int tid = threadIdx.x;
    const int s0 = blockIdx.x * 64;
    const int b  = blockIdx.y;
    const int d  = blockIdx.z;
    const float* w  = d ? wr : wf;
    const float* bi = d ? bir : bif;
    const float* bh = d ? bhr : bhf;

    const int sn  = tid & 127, skq = tid >> 7;
    const int xr  = tid & 63,  xkq = tid >> 6;
    int s = s0 + xr;
    int tsrc = d ? (1023 - s) : s;
    const float* wptr = w + sn * 64 + skq * 16;
    const float* hptr = g_h0 + ((size_t)b * 1024 + tsrc) * 64 + xkq * 8;

    const int nq = tid & 15;
    const int bq = tid >> 4;
    U64 acc[4][4];
    #pragma unroll
    for (int i = 0; i < 4; i++)
        #pragma unroll
        for (int j = 0; j < 4; j++) acc[i][j] = 0ull;

    #pragma unroll
    for (int ch = 0; ch < 2; ch++){
        if (ch){ __syncthreads(); }
        {
            const float4* src = (const float4*)(wptr + ch * 32);
            float4 v0 = src[0], v1 = src[1], v2 = src[2], v3 = src[3];
            int kb = skq * 16;
            ws[(kb+ 0)*TW + sn] = v0.x; ws[(kb+ 1)*TW + sn] = v0.y;
            ws[(kb+ 2)*TW + sn] = v0.z; ws[(kb+ 3)*TW + sn] = v0.w;
            ws[(kb+ 4)*TW + sn] = v1.x; ws[(kb+ 5)*TW + sn] = v1.y;
            ws[(kb+ 6)*TW + sn] = v1.z; ws[(kb+ 7)*TW + sn] = v1.w;
            ws[(kb+ 8)*TW + sn] = v2.x; ws[(kb+ 9)*TW + sn] = v2.y;
            ws[(kb+10)*TW + sn] = v2.z; ws[(kb+11)*TW + sn] = v2.w;
            ws[(kb+12)*TW + sn] = v3.x; ws[(kb+13)*TW + sn] = v3.y;
            ws[(kb+14)*TW + sn] = v3.z; ws[(kb+15)*TW + sn] = v3.w;
        }
        {
            const float4* src = (const float4*)(hptr + ch * 32);
            float4 u0 = src[0], u1 = src[1];
            int kb = xkq * 8;
            *(float2*)&fs[(kb+0)*TW + 2*xr] = make_float2(u0.x, u0.x);
            *(float2*)&fs[(kb+1)*TW + 2*xr] = make_float2(u0.y, u0.y);
            *(float2*)&fs[(kb+2)*TW + 2*xr] = make_float2(u0.z, u0.z);
            *(float2*)&fs[(kb+3)*TW + 2*xr] = make_float2(u0.w, u0.w);
            *(float2*)&fs[(kb+4)*TW + 2*xr] = make_float2(u1.x, u1.x);
            *(float2*)&fs[(kb+5)*TW + 2*xr] = make_float2(u1.y, u1.y);
            *(float2*)&fs[(kb+6)*TW + 2*xr] = make_float2(u1.z, u1.z);
            *(float2*)&fs[(kb+7)*TW + 2*xr] = make_float2(u1.w, u1.w);
        }
        __syncthreads();
        #pragma unroll
        for (int kk = 0; kk < 32; kk++){
            ulonglong2 wa = *(const ulonglong2*)&ws[kk*TW + nq*4];
            ulonglong2 wb = *(const ulonglong2*)&ws[kk*TW + 64 + nq*4];
            ulonglong2 xa = *(const ulonglong2*)&fs[kk*TW + bq*8];
            ulonglong2 xc = *(const ulonglong2*)&fs[kk*TW + bq*8 + 4];
            U64 xv0 = xa.x, xv1 = xa.y, xv2 = xc.x, xv3 = xc.y;
            ffma2(acc[0][0], xv0, wa.x); ffma2(acc[0][1], xv0, wa.y);
            ffma2(acc[0][2], xv0, wb.x); ffma2(acc[0][3], xv0, wb.y);
            ffma2(acc[1][0], xv1, wa.x); ffma2(acc[1][1], xv1, wa.y);
            ffma2(acc[1][2], xv1, wb.x); ffma2(acc[1][3], xv1, wb.y);
            ffma2(acc[2][0], xv2, wa.x); ffma2(acc[2][1], xv2, wa.y);
            ffma2(acc[2][2], xv2, wb.x); ffma2(acc[2][3], xv2, wb.y);
            ffma2(acc[3][0], xv3, wa.x); ffma2(acc[3][1], xv3, wa.y);
            ffma2(acc[3][2], xv3, wb.x); ffma2(acc[3][3], xv3, wb.y);
        }
    }

    int j0 = nq * 4, j1 = 64 + nq * 4;
    float bv[8];
    #pragma unroll
    for (int q = 0; q < 4; q++){ bv[q] = bi[j0+q] + bh[j0+q]; bv[4+q] = bi[j1+q] + bh[j1+q]; }

    float* base = g_xp + ((size_t)(d * 64 + b) * 1024 + s0) * 128;
    #pragma unroll
    for (int b4 = 0; b4 < 4; b4++){
        float* dst = base + (size_t)(bq * 4 + b4) * 128;
        float2 v0 = unpk(acc[b4][0]); v0.x += bv[0]; v0.y += bv[1];
        float2 v1 = unpk(acc[b4][1]); v1.x += bv[2]; v1.y += bv[3];
        float2 v2 = unpk(acc[b4][2]); v2.x += bv[4]; v2.y += bv[5];
        float2 v3 = unpk(acc[b4][3]); v3.x += bv[6]; v3.y += bv[7];
        *(float2*)(dst + j0)     = v0;
        *(float2*)(dst + j0 + 2) = v1;
        *(float2*)(dst + j1)     = v2;
        *(float2*)(dst + j1 + 2) = v3;
    }
}

// ---------------- LSTM: 4 warps/(dir,batch), one barrier/step ----------------
__global__ void __launch_bounds__(128, 1) lstm_kernel(
    const float* __restrict__ whh_f, const float* __restrict__ whh_r, int outsel)
{
    const int blk = blockIdx.x;
    const int d = blk >> 6, b = blk & 63;
    const int tid = threadIdx.x;
    const int g = tid >> 5;
    const int hh = tid & 31;
    float* hout = outsel ? g_h1 : g_h0;
    const float* whh = d ? whh_r : whh_f;

    U64 wp[16];
    {
        const ulonglong2* wr2 = (const ulonglong2*)(whh + (g * 32 + hh) * 32);
        #pragma unroll
        for (int r = 0; r < 8; r++){ ulonglong2 v = wr2[r]; wp[2*r] = v.x; wp[2*r+1] = v.y; }
    }

    __shared__ __align__(16) float hs[32];
    __shared__ __align__(16) float gbuf[2][128];
    if (tid < 32) hs[tid] = 0.0f;
    float c = 0.0f;
    __syncthreads();

    const float* xq = g_xp + (size_t)(d * 64 + b) * 1024 * 128 + g * 32 + hh;
    float cur = xq[0];
    float nxt = xq[128];

    float* outp = hout + (size_t)b * 1024 * 64 + d * 32 + hh;

    for (int s = 0; s < 1024; s++){
        float nn = 0.0f;
        if (s + 2 < 1024) nn = xq[(size_t)(s + 2) * 128];

        U64 a0 = 0ull, a1 = 0ull;
        const ulonglong2* h2 = (const ulonglong2*)hs;
        #pragma unroll
        for (int r = 0; r < 8; r++){
            ulonglong2 hv = h2[r];
            ffma2(a0, hv.x, wp[2*r]);
            ffma2(a1, hv.y, wp[2*r+1]);
        }
        float pre = cur + sum2(add2(a0, a1));
        float act = (g == 2) ? tanhx(pre) : sigf(pre);
        float* gb = gbuf[s & 1];
        gb[g * 32 + hh] = act;
        __syncthreads();

        float iv = gb[hh];
        float fv = gb[32 + hh];
        float gv = gb[64 + hh];
        float ov = gb[96 + hh];
        c = fmaf(fv, c, iv * gv);
        float hval = ov * tanhx(c);
        hs[hh] = hval;
        __syncwarp();
        if (g == 0){
            int tout = d ? (1023 - s) : s;
            outp[(size_t)tout * 64] = hval;
        }
        cur = nxt; nxt = nn;
    }
}

// ---------------- fc1 via mma.sync bf16 3-term split ----------------
// D[64 batch, 128 wrow] += X[64,k] * W[128,k]^T; grid (16 wrow-tiles, 64 k-splits)
#define MB_WH 0
#define MB_WL 8192
#define MB_XH 16384
#define MB_XL 20480
#define MB_BUF 24576

__global__ void __launch_bounds__(128) fc1_mma_kernel(const float* __restrict__ W)
{
    __shared__ __align__(128) char smb[2 * MB_BUF];  // 48KB
    const int tid  = threadIdx.x;
    const int lane = tid & 31;
    const int wid  = tid >> 5;
    const int m0out  = blockIdx.x * 128;
    const int kstart = blockIdx.y * 1024;
    const float* X = g_h1;

    const int kq    = tid & 7;     // float4 index in 32-k row
    const int rbase = tid >> 3;    // 0..15

    const float* wg = W + (size_t)(m0out + rbase) * 65536 + kstart + kq * 4;
    const float* xg = X + (size_t)rbase * 65536 + kstart + kq * 4;

    const uint32_t sb = smem_u32(smb);

    // ldmatrix lane constants (A = X tile, B = W tile)
    const int arow = wid * 16 + ((lane >> 3) & 1) * 8 + (lane & 7);
    const int asw  = (arow >> 1) & 3;
    const int akb  = lane >> 4;                 // k-half select
    const uint32_t aoff = (uint32_t)(arow * 64);
    const int brow = ((lane >> 4) & 1) * 8 + (lane & 7);
    const int bsw  = (brow >> 1) & 3;
    const int bkb  = (lane >> 3) & 1;
    const uint32_t boff = (uint32_t)(brow * 64);

    float acc[16][4];
    #pragma unroll
    for (int i = 0; i < 16; i++)
        #pragma unroll
        for (int j = 0; j < 4; j++) acc[i][j] = 0.0f;

    float4 wv[8], xv[4];
    #pragma unroll
    for (int i = 0; i < 8; i++) wv[i] = *(const float4*)(wg + (size_t)i * 16 * 65536);
    #pragma unroll
    for (int i = 0; i < 4; i++) xv[i] = *(const float4*)(xg + (size_t)i * 16 * 65536);

    const int so_base = (kq & 1) * 8;   // within-chunk byte offset of this kq's pair
    for (int ch = 0; ch < 32; ch++){
        char* bufc = smb + (ch & 1) * MB_BUF;
        // convert + swizzled STS (hi & lo tiles)
        #pragma unroll
        for (int i = 0; i < 8; i++){
            float4 v = wv[i];
            int row = rbase + i * 16;
            uint32_t h0 = cvt_bf2(v.x, v.y);
            uint32_t l0 = cvt_bf2(v.x - __uint_as_float(h0 << 16),
                                  v.y - __uint_as_float(h0 & 0xFFFF0000u));
            uint32_t h1 = cvt_bf2(v.z, v.w);
            uint32_t l1 = cvt_bf2(v.z - __uint_as_float(h1 << 16),
                                  v.w - __uint_as_float(h1 & 0xFFFF0000u));
            int so = row * 64 + ((((kq >> 1) ^ ((row >> 1) & 3)) << 4) | so_base);
            *(uint2*)(bufc + MB_WH + so) = make_uint2(h0, h1);
            *(uint2*)(bufc + MB_WL + so) = make_uint2(l0, l1);
        }
        #pragma unroll
        for (int i = 0; i < 4; i++){
            float4 v = xv[i];
            int row = rbase + i * 16;
            uint32_t h0 = cvt_bf2(v.x, v.y);
            uint32_t l0 = cvt_bf2(v.x - __uint_as_float(h0 << 16),
                                  v.y - __uint_as_float(h0 & 0xFFFF0000u));
            uint32_t h1 = cvt_bf2(v.z, v.w);
            uint32_t l1 = cvt_bf2(v.z - __uint_as_float(h1 << 16),
                                  v.w - __uint_as_float(h1 & 0xFFFF0000u));
            int so = row * 64 + ((((kq >> 1) ^ ((row >> 1) & 3)) << 4) | so_base);
            *(uint2*)(bufc + MB_XH + so) = make_uint2(h0, h1);
            *(uint2*)(bufc + MB_XL + so) = make_uint2(l0, l1);
        }
        __syncthreads();

        if (ch + 1 < 32){   // prefetch next chunk (in flight over the MMA section)
            #pragma unroll
            for (int i = 0; i < 8; i++) wv[i] = *(const float4*)(wg + (size_t)i * 16 * 65536 + (ch + 1) * 32);
            #pragma unroll
            for (int i = 0; i < 4; i++) xv[i] = *(const float4*)(xg + (size_t)i * 16 * 65536 + (ch + 1) * 32);
        }

        const uint32_t sbuf = sb + (ch & 1) * MB_BUF;
        #pragma unroll
        for (int kt = 0; kt < 2; kt++){
            uint32_t ahi[4], alo[4];
            uint32_t aaddr = sbuf + MB_XH + aoff + (uint32_t)((((kt << 1) | akb) ^ asw) << 4);
            ldm4(ahi, aaddr);
            ldm4(alo, aaddr + (MB_XL - MB_XH));
            #pragma unroll
            for (int ntp = 0; ntp < 8; ntp++){
                uint32_t bhi[4], blo[4];
                uint32_t baddr = sbuf + MB_WH + (uint32_t)(ntp * 1024) + boff
                               + (uint32_t)((((kt << 1) | bkb) ^ bsw) << 4);
                ldm4(bhi, baddr);
                ldm4(blo, baddr + (MB_WL - MB_WH));
                mma_bf(acc[2*ntp],   ahi, bhi[0], bhi[1]);
                mma_bf(acc[2*ntp],   alo, bhi[0], bhi[1]);
                mma_bf(acc[2*ntp],   ahi, blo[0], blo[1]);
                mma_bf(acc[2*ntp+1], ahi, bhi[2], bhi[3]);
                mma_bf(acc[2*ntp+1], alo, bhi[2], bhi[3]);
                mma_bf(acc[2*ntp+1], ahi, blo[2], blo[3]);
            }
        }
        __syncthreads();
    }

    // epilogue: d0,d1 -> (batch, wrow|wrow+1); d2,d3 -> batch+8
    {
        int bat  = wid * 16 + (lane >> 2);
        int colb = m0out + (lane & 3) * 2;
        float* d0 = g_part1 + ((size_t)blockIdx.y * 64 + bat) * 2048 + colb;
        float* d1 = d0 + (size_t)8 * 2048;
        #pragma unroll
        for (int nt = 0; nt < 16; nt++){
            *(float2*)(d0 + nt * 8) = make_float2(acc[nt][0], acc[nt][1]);
            *(float2*)(d1 + nt * 8) = make_float2(acc[nt][2], acc[nt][3]);
        }
    }
}

// ---------------- fc GEMM v3 (fp32 f32x2) — used for fc2 ----------------
#define WS3 264
#define FS3 68

__global__ void __launch_bounds__(256) fc_kernel(
    const float* __restrict__ W, int sel, int N, int K, int kPerSplit)
{
    const float* __restrict__ X = sel ? g_hidden : g_h1;
    float* __restrict__ part = sel ? g_part2 : g_part1;

    __shared__ float ws[2][16 * WS3];
    __shared__ float fs[2][16 * FS3];

    const int tid = threadIdx.x;
    const int nq = tid & 31;
    const int bq = tid >> 5;
    const int nbase = blockIdx.x * 256;
    const int kstart = blockIdx.y * kPerSplit;

    const float* wptr = W + (size_t)(nbase + tid) * K + kstart;
    const int xb = tid & 63, xkq = tid >> 6;
    const float* xptr = X + (size_t)xb * K + kstart + xkq * 4;

    U64 acc[8][4];
    #pragma unroll
    for (int i = 0; i < 8; i++)
        #pragma unroll
        for (int j = 0; j < 4; j++) acc[i][j] = 0ull;

    float4 w0, w1, w2, w3, xv;
    {
        const float4* sw = (const float4*)wptr;
        w0 = sw[0]; w1 = sw[1]; w2 = sw[2]; w3 = sw[3];
        xv = *(const float4*)xptr;
    }

    const int nchunk = kPerSplit / 16;
    for (int ch = 0; ch < nchunk; ch++){
        const int buf = ch & 1;
        {
            float* wsb = ws[buf];
            wsb[ 0*WS3 + tid] = w0.x; wsb[ 1*WS3 + tid] = w0.y;
            wsb[ 2*WS3 + tid] = w0.z; wsb[ 3*WS3 + tid] = w0.w;
            wsb[ 4*WS3 + tid] = w1.x; wsb[ 5*WS3 + tid] = w1.y;
            wsb[ 6*WS3 + tid] = w1.z; wsb[ 7*WS3 + tid] = w1.w;
            wsb[ 8*WS3 + tid] = w2.x; wsb[ 9*WS3 + tid] = w2.y;
            wsb[10*WS3 + tid] = w2.z; wsb[11*WS3 + tid] = w2.w;
            wsb[12*WS3 + tid] = w3.x; wsb[13*WS3 + tid] = w3.y;
            wsb[14*WS3 + tid] = w3.z; wsb[15*WS3 + tid] = w3.w;
            float* fsb = fs[buf];
            int kb = xkq * 4;
            fsb[(kb+0)*FS3 + xb] = xv.x; fsb[(kb+1)*FS3 + xb] = xv.y;
            fsb[(kb+2)*FS3 + xb] = xv.z; fsb[(kb+3)*FS3 + xb] = xv.w;
        }
        __syncthreads();
        if (ch + 1 < nchunk){
            const float4* sw = (const float4*)(wptr + (ch + 1) * 16);
            w0 = sw[0]; w1 = sw[1]; w2 = sw[2]; w3 = sw[3];
            xv = *(const float4*)(xptr + (ch + 1) * 16);
        }
        const float* wsb = ws[buf];
        const float* fsb = fs[buf];
        #pragma unroll
        for (int kk = 0; kk < 16; kk++){
            const float* wrow = wsb + kk * WS3 + nq * 8;
            ulonglong2 wA = *(const ulonglong2*)(wrow);
            ulonglong2 wB = *(const ulonglong2*)(wrow + 4);
            const float* xrow = fsb + kk * FS3 + bq * 8;
            float4 xa = *(const float4*)(xrow);
            float4 xc = *(const float4*)(xrow + 4);
            U64 xd0 = pack2(xa.x, xa.x), xd1 = pack2(xa.y, xa.y);
            U64 xd2 = pack2(xa.z, xa.z), xd3 = pack2(xa.w, xa.w);
            U64 xd4 = pack2(xc.x, xc.x), xd5 = pack2(xc.y, xc.y);
            U64 xd6 = pack2(xc.z, xc.z), xd7 = pack2(xc.w, xc.w);
            ffma2(acc[0][0], xd0, wA.x); ffma2(acc[0][1], xd0, wA.y);
            ffma2(acc[0][2], xd0, wB.x); ffma2(acc[0][3], xd0, wB.y);
            ffma2(acc[1][0], xd1, wA.x); ffma2(acc[1][1], xd1, wA.y);
            ffma2(acc[1][2], xd1, wB.x); ffma2(acc[1][3], xd1, wB.y);
            ffma2(acc[2][0], xd2, wA.x); ffma2(acc[2][1], xd2, wA.y);
            ffma2(acc[2][2], xd2, wB.x); ffma2(acc[2][3], xd2, wB.y);
            ffma2(acc[3][0], xd3, wA.x); ffma2(acc[3][1], xd3, wA.y);
            ffma2(acc[3][2], xd3, wB.x); ffma2(acc[3][3], xd3, wB.y);
            ffma2(acc[4][0], xd4, wA.x); ffma2(acc[4][1], xd4, wA.y);
            ffma2(acc[4][2], xd4, wB.x); ffma2(acc[4][3], xd4, wB.y);
            ffma2(acc[5][0], xd5, wA.x); ffma2(acc[5][1], xd5, wA.y);
            ffma2(acc[5][2], xd5, wB.x); ffma2(acc[5][3], xd5, wB.y);
            ffma2(acc[6][0], xd6, wA.x); ffma2(acc[6][1], xd6, wA.y);
            ffma2(acc[6][2], xd6, wB.x); ffma2(acc[6][3], xd6, wB.y);
            ffma2(acc[7][0], xd7, wA.x); ffma2(acc[7][1], xd7, wA.y);
            ffma2(acc[7][2], xd7, wB.x); ffma2(acc[7][3], xd7, wB.y);
        }
        __syncthreads();
    }

    #pragma unroll
    for (int bb = 0; bb < 8; bb++){
        int b = bq * 8 + bb;
        float* dst = part + ((size_t)blockIdx.y * 64 + b) * N + nbase + nq * 8;
        ulonglong2 s0, s1;
        s0.x = acc[bb][0]; s0.y = acc[bb][1];
        s1.x = acc[bb][2]; s1.y = acc[bb][3];
        *(ulonglong2*)(dst)     = s0;
        *(ulonglong2*)(dst + 4) = s1;
    }
}

// ---------------- split-K reductions ----------------
__global__ void reduce1_kernel(const float* __restrict__ bias){
    int i = blockIdx.x * 256 + threadIdx.x;   // 131072
    int m = i & 2047, b = i >> 11;
    float acc = bias[m];
    #pragma unroll
    for (int s = 0; s < 64; s++) acc += g_part1[((size_t)s * 64 + b) * 2048 + m];
    g_hidden[i] = fmaxf(acc, 0.0f);
}

__global__ void reduce2_kernel(const float* __restrict__ bias, float* __restrict__ out){
    int i = blockIdx.x * 256 + threadIdx.x;   // 589824
    int n = i % 9216, b = i / 9216;
    float acc = bias[n];
    #pragma unroll
    for (int s = 0; s < 4; s++) acc += g_part2[((size_t)s * 64 + b) * 9216 + n];
    out[i] = acc;
}

// ---------------- launcher ----------------
extern "C" void kernel_launch(void* const* d_in, const int* in_sizes, int n_in,
                              void* d_out, int out_size)
{
    const float* x     = (const float*)d_in[0];
    const float* wih0  = (const float*)d_in[1];
    const float* whh0  = (const float*)d_in[2];
    const float* bih0  = (const float*)d_in[3];
    const float* bhh0  = (const float*)d_in[4];
    const float* wih0r = (const float*)d_in[5];
    const float* whh0r = (const float*)d_in[6];
    const float* bih0r = (const float*)d_in[7];
    const float* bhh0r = (const float*)d_in[8];
    const float* wih1  = (const float*)d_in[9];
    const float* whh1  = (const float*)d_in[10];
    const float* bih1  = (const float*)d_in[11];
    const float* bhh1  = (const float*)d_in[12];
    const float* wih1r = (const float*)d_in[13];
    const float* whh1r = (const float*)d_in[14];
    const float* bih1r = (const float*)d_in[15];
    const float* bhh1r = (const float*)d_in[16];
    const float* fc1w  = (const float*)d_in[17];
    const float* fc1b  = (const float*)d_in[18];
    const float* fc2w  = (const float*)d_in[19];
    const float* fc2b  = (const float*)d_in[20];
    float* out = (float*)d_out;

    xproj0_kernel<<<dim3(16, 64, 2), 256>>>(x, wih0, bih0, bhh0, wih0r, bih0r, bhh0r);
    lstm_kernel<<<128, 128>>>(whh0, whh0r, 0);
    xproj1_kernel<<<dim3(16, 64, 2), 256>>>(wih1, bih1, bhh1, wih1r, bih1r, bhh1r);
    lstm_kernel<<<128, 128>>>(whh1, whh1r, 1);

    // fc1 via mma.sync: grid (16 wrow-tiles of 128, 64 k-splits of 1024)
    fc1_mma_kernel<<<dim3(16, 64), 128>>>(fc1w);
    reduce1_kernel<<<512, 256>>>(fc1b);

    // fc2: N=9216 (36 n-blocks), K=2048, split-K=4 -> grid (36, 4)
    fc_kernel<<<dim3(36, 4), 256>>>(fc2w, 1, 9216, 2048, 512);
    reduce2_kernel<<<2304, 256>>>(fc2b, out);
}

// round 12
// speedup vs baseline: 1.8969x; 1.1029x over previous
#include <cuda_runtime.h>
#include <cstdint>

typedef unsigned long long U64;

// ---------------- static device scratch ----------------
__device__ float g_xp[16777472];   // [2][64][1024][128] + 256 pad (prefetch overrun)
__device__ float g_h0[4194304];    // [64][1024][64]
__device__ float g_h1[4194304];    // [64][1024][64]
__device__ float g_part1[8388608]; // [64][64][2048] fc1 split-K partials
__device__ float g_hidden[131072]; // [64][2048]
__device__ float g_part2[2359296]; // [4][64][9216] fc2 split-K partials

// ---------------- helpers ----------------
__device__ __forceinline__ void ffma2(U64 &acc, U64 a, U64 b){
    asm("fma.rn.f32x2 %0, %1, %2, %0;" : "+l"(acc) : "l"(a), "l"(b));
}
__device__ __forceinline__ U64 add2(U64 a, U64 b){
    U64 r; asm("add.rn.f32x2 %0, %1, %2;" : "=l"(r) : "l"(a), "l"(b)); return r;
}
__device__ __forceinline__ float2 unpk(U64 v){
    float2 r; asm("mov.b64 {%0, %1}, %2;" : "=f"(r.x), "=f"(r.y) : "l"(v)); return r;
}
__device__ __forceinline__ U64 pack2(float lo, float hi){
    U64 r; asm("mov.b64 %0, {%1, %2};" : "=l"(r) : "f"(lo), "f"(hi)); return r;
}
__device__ __forceinline__ float sum2(U64 v){ float2 r = unpk(v); return r.x + r.y; }
__device__ __forceinline__ float fex2(float x){ float r; asm("ex2.approx.ftz.f32 %0, %1;" : "=f"(r) : "f"(x)); return r; }
__device__ __forceinline__ float frcp(float x){ float r; asm("rcp.approx.ftz.f32 %0, %1;" : "=f"(r) : "f"(x)); return r; }
__device__ __forceinline__ float sigf (float x){ return frcp(1.0f + fex2(-1.4426950408889634f * x)); }
__device__ __forceinline__ float tanhx(float x){ return fmaf(-2.0f, frcp(1.0f + fex2(2.8853900817779268f * x)), 1.0f); }
// fast single-MUFU activations (lstm recurrence only)
__device__ __forceinline__ float tanha(float x){ float r; asm("tanh.approx.f32 %0, %1;" : "=f"(r) : "f"(x)); return r; }
__device__ __forceinline__ float siga (float x){ return fmaf(0.5f, tanha(0.5f * x), 0.5f); }

// cvt: word = { hi16: bf16(b), lo16: bf16(a) }
__device__ __forceinline__ uint32_t cvt_bf2(float a, float b){
    uint32_t r; asm("cvt.rn.bf16x2.f32 %0, %1, %2;" : "=r"(r) : "f"(b), "f"(a)); return r;
}
__device__ __forceinline__ uint32_t smem_u32(const void* p){
    uint32_t a; asm("{ .reg .u64 t; cvta.to.shared.u64 t, %1; cvt.u32.u64 %0, t; }" : "=r"(a) : "l"(p));
    return a;
}
__device__ __forceinline__ void ldm4(uint32_t* r, uint32_t addr){
    asm volatile("ldmatrix.sync.aligned.m8n8.x4.shared.b16 {%0,%1,%2,%3}, [%4];"
        : "=r"(r[0]), "=r"(r[1]), "=r"(r[2]), "=r"(r[3]) : "r"(addr));
}
__device__ __forceinline__ void mma_bf(float (&d)[4], const uint32_t* a, uint32_t b0, uint32_t b1){
    asm volatile("mma.sync.aligned.m16n8k16.row.col.f32.bf16.bf16.f32 "
        "{%0,%1,%2,%3}, {%4,%5,%6,%7}, {%8,%9}, {%0,%1,%2,%3};"
        : "+f"(d[0]), "+f"(d[1]), "+f"(d[2]), "+f"(d[3])
        : "r"(a[0]), "r"(a[1]), "r"(a[2]), "r"(a[3]), "r"(b0), "r"(b1));
}

#define TW 132   // padded smem row stride (floats) for xproj kernels

// ---------------- xproj layer 0: tiled, K=9 ----------------
__global__ void __launch_bounds__(256) xproj0_kernel(const float* __restrict__ x,
    const float* __restrict__ wf, const float* __restrict__ bif, const float* __restrict__ bhf,
    const float* __restrict__ wr, const float* __restrict__ bir, const float* __restrict__ bhr)
{
    __shared__ float ws[9 * TW];
    __shared__ float fs[9 * TW];
    const int tid = threadIdx.x;
    const int s0 = blockIdx.x * 64;
    const int b  = blockIdx.y;
    const int d  = blockIdx.z;
    const float* w  = d ? wr : wf;
    const float* bi = d ? bir : bif;
    const float* bh = d ? bhr : bhf;

    if (tid < 128){
        const float* src = w + tid * 9;
        #pragma unroll
        for (int k = 0; k < 9; k++) ws[k * TW + tid] = src[k];
    } else if (tid < 192){
        int r = tid - 128;
        int s = s0 + r;
        int tsrc = d ? (1023 - s) : s;
        const float* src = x + ((size_t)b * 1024 + tsrc) * 9;
        #pragma unroll
        for (int k = 0; k < 9; k++){
            float v = src[k];
            *(float2*)&fs[k * TW + 2 * r] = make_float2(v, v);
        }
    }
    __syncthreads();

    const int nq = tid & 15;
    const int bq = tid >> 4;
    U64 acc[4][4];
    #pragma unroll
    for (int i = 0; i < 4; i++)
        #pragma unroll
        for (int j = 0; j < 4; j++) acc[i][j] = 0ull;

    #pragma unroll
    for (int kk = 0; kk < 9; kk++){
        ulonglong2 wa = *(const ulonglong2*)&ws[kk*TW + nq*4];
        ulonglong2 wb = *(const ulonglong2*)&ws[kk*TW + 64 + nq*4];
        ulonglong2 xa = *(const ulonglong2*)&fs[kk*TW + bq*8];
        ulonglong2 xc = *(const ulonglong2*)&fs[kk*TW + bq*8 + 4];
        U64 xv0 = xa.x, xv1 = xa.y, xv2 = xc.x, xv3 = xc.y;
        ffma2(acc[0][0], xv0, wa.x); ffma2(acc[0][1], xv0, wa.y);
        ffma2(acc[0][2], xv0, wb.x); ffma2(acc[0][3], xv0, wb.y);
        ffma2(acc[1][0], xv1, wa.x); ffma2(acc[1][1], xv1, wa.y);
        ffma2(acc[1][2], xv1, wb.x); ffma2(acc[1][3], xv1, wb.y);
        ffma2(acc[2][0], xv2, wa.x); ffma2(acc[2][1], xv2, wa.y);
        ffma2(acc[2][2], xv2, wb.x); ffma2(acc[2][3], xv2, wb.y);
        ffma2(acc[3][0], xv3, wa.x); ffma2(acc[3][1], xv3, wa.y);
        ffma2(acc[3][2], xv3, wb.x); ffma2(acc[3][3], xv3, wb.y);
    }

    int j0 = nq * 4, j1 = 64 + nq * 4;
    float bv[8];
    #pragma unroll
    for (int q = 0; q < 4; q++){ bv[q] = bi[j0+q] + bh[j0+q]; bv[4+q] = bi[j1+q] + bh[j1+q]; }

    float* base = g_xp + ((size_t)(d * 64 + b) * 1024 + s0) * 128;
    #pragma unroll
    for (int b4 = 0; b4 < 4; b4++){
        float* dst = base + (size_t)(bq * 4 + b4) * 128;
        float2 v0 = unpk(acc[b4][0]); v0.x += bv[0]; v0.y += bv[1];
        float2 v1 = unpk(acc[b4][1]); v1.x += bv[2]; v1.y += bv[3];
        float2 v2 = unpk(acc[b4][2]); v2.x += bv[4]; v2.y += bv[5];
        float2 v3 = unpk(acc[b4][3]); v3.x += bv[6]; v3.y += bv[7];
        *(float2*)(dst + j0)     = v0;
        *(float2*)(dst + j0 + 2) = v1;
        *(float2*)(dst + j1)     = v2;
        *(float2*)(dst + j1 + 2) = v3;
    }
}

// ---------------- xproj layer 1: tiled GEMM, K=64 ----------------
__global__ void __launch_bounds__(256) xproj1_kernel(
    const float* __restrict__ wf, const float* __restrict__ bif, const float* __restrict__ bhf,
    const float* __restrict__ wr, const float* __restrict__ bir, const float* __restrict__ bhr)
{
    __shared__ float ws[32 * TW];
    __shared__ float fs[32 * TW];
    const int tid = threadIdx.x;
    const int s0 = blockIdx.x * 64;
    const int b  = blockIdx.y;
    const int d  = blockIdx.z;
    const float* w  = d ? wr : wf;
    const float* bi = d ? bir : bif;
    const float* bh = d ? bhr : bhf;

    const int sn  = tid & 127, skq = tid >> 7;
    const int xr  = tid & 63,  xkq = tid >> 6;
    int s = s0 + xr;
    int tsrc = d ? (1023 - s) : s;
    const float* wptr = w + sn * 64 + skq * 16;
    const float* hptr = g_h0 + ((size_t)b * 1024 + tsrc) * 64 + xkq * 8;

    const int nq = tid & 15;
    const int bq = tid >> 4;
    U64 acc[4][4];
    #pragma unroll
    for (int i = 0; i < 4; i++)
        #pragma unroll
        for (int j = 0; j < 4; j++) acc[i][j] = 0ull;

    #pragma unroll
    for (int ch = 0; ch < 2; ch++){
        if (ch){ __syncthreads(); }
        {
            const float4* src = (const float4*)(wptr + ch * 32);
            float4 v0 = src[0], v1 = src[1], v2 = src[2], v3 = src[3];
            int kb = skq * 16;
            ws[(kb+ 0)*TW + sn] = v0.x; ws[(kb+ 1)*TW + sn] = v0.y;
            ws[(kb+ 2)*TW + sn] = v0.z; ws[(kb+ 3)*TW + sn] = v0.w;
            ws[(kb+ 4)*TW + sn] = v1.x; ws[(kb+ 5)*TW + sn] = v1.y;
            ws[(kb+ 6)*TW + sn] = v1.z; ws[(kb+ 7)*TW + sn] = v1.w;
            ws[(kb+ 8)*TW + sn] = v2.x; ws[(kb+ 9)*TW + sn] = v2.y;
            ws[(kb+10)*TW + sn] = v2.z; ws[(kb+11)*TW + sn] = v2.w;
            ws[(kb+12)*TW + sn] = v3.x; ws[(kb+13)*TW + sn] = v3.y;
            ws[(kb+14)*TW + sn] = v3.z; ws[(kb+15)*TW + sn] = v3.w;
        }
        {
            const float4* src = (const float4*)(hptr + ch * 32);
            float4 u0 = src[0], u1 = src[1];
            int kb = xkq * 8;
            *(float2*)&fs[(kb+0)*TW + 2*xr] = make_float2(u0.x, u0.x);
            *(float2*)&fs[(kb+1)*TW + 2*xr] = make_float2(u0.y, u0.y);
            *(float2*)&fs[(kb+2)*TW + 2*xr] = make_float2(u0.z, u0.z);
            *(float2*)&fs[(kb+3)*TW + 2*xr] = make_float2(u0.w, u0.w);
            *(float2*)&fs[(kb+4)*TW + 2*xr] = make_float2(u1.x, u1.x);
            *(float2*)&fs[(kb+5)*TW + 2*xr] = make_float2(u1.y, u1.y);
            *(float2*)&fs[(kb+6)*TW + 2*xr] = make_float2(u1.z, u1.z);
            *(float2*)&fs[(kb+7)*TW + 2*xr] = make_float2(u1.w, u1.w);
        }
        __syncthreads();
        #pragma unroll
        for (int kk = 0; kk < 32; kk++){
            ulonglong2 wa = *(const ulonglong2*)&ws[kk*TW + nq*4];
            ulonglong2 wb = *(const ulonglong2*)&ws[kk*TW + 64 + nq*4];
            ulonglong2 xa = *(const ulonglong2*)&fs[kk*TW + bq*8];
            ulonglong2 xc = *(const ulonglong2*)&fs[kk*TW + bq*8 + 4];
            U64 xv0 = xa.x, xv1 = xa.y, xv2 = xc.x, xv3 = xc.y;
            ffma2(acc[0][0], xv0, wa.x); ffma2(acc[0][1], xv0, wa.y);
            ffma2(acc[0][2], xv0, wb.x); ffma2(acc[0][3], xv0, wb.y);
            ffma2(acc[1][0], xv1, wa.x); ffma2(acc[1][1], xv1, wa.y);
            ffma2(acc[1][2], xv1, wb.x); ffma2(acc[1][3], xv1, wb.y);
            ffma2(acc[2][0], xv2, wa.x); ffma2(acc[2][1], xv2, wa.y);
            ffma2(acc[2][2], xv2, wb.x); ffma2(acc[2][3], xv2, wb.y);
            ffma2(acc[3][0], xv3, wa.x); ffma2(acc[3][1], xv3, wa.y);
            ffma2(acc[3][2], xv3, wb.x); ffma2(acc[3][3], xv3, wb.y);
        }
    }

    int j0 = nq * 4, j1 = 64 + nq * 4;
    float bv[8];
    #pragma unroll
    for (int q = 0; q < 4; q++){ bv[q] = bi[j0+q] + bh[j0+q]; bv[4+q] = bi[j1+q] + bh[j1+q]; }

    float* base = g_xp + ((size_t)(d * 64 + b) * 1024 + s0) * 128;
    #pragma unroll
    for (int b4 = 0; b4 < 4; b4++){
        float* dst = base + (size_t)(bq * 4 + b4) * 128;
        float2 v0 = unpk(acc[b4][0]); v0.x += bv[0]; v0.y += bv[1];
        float2 v1 = unpk(acc[b4][1]); v1.x += bv[2]; v1.y += bv[3];
        float2 v2 = unpk(acc[b4][2]); v2.x += bv[4]; v2.y += bv[5];
        float2 v3 = unpk(acc[b4][3]); v3.x += bv[6]; v3.y += bv[7];
        *(float2*)(dst + j0)     = v0;
        *(float2*)(dst + j0 + 2) = v1;
        *(float2*)(dst + j1)     = v2;
        *(float2*)(dst + j1 + 2) = v3;
    }
}

// ---------------- LSTM: 4 warps/(dir,batch), one barrier/step, tanh.approx ----------------
__global__ void __launch_bounds__(128, 1) lstm_kernel(
    const float* __restrict__ whh_f, const float* __restrict__ whh_r, int outsel)
{
    const int blk = blockIdx.x;
    const int d = blk >> 6, b = blk & 63;
    const int tid = threadIdx.x;
    const int g = tid >> 5;
    const int hh = tid & 31;
    float* hout = outsel ? g_h1 : g_h0;
    const float* whh = d ? whh_r : whh_f;

    U64 wp[16];
    {
        const ulonglong2* wr2 = (const ulonglong2*)(whh + (g * 32 + hh) * 32);
        #pragma unroll
        for (int r = 0; r < 8; r++){ ulonglong2 v = wr2[r]; wp[2*r] = v.x; wp[2*r+1] = v.y; }
    }

    __shared__ __align__(16) float hs[32];
    __shared__ __align__(16) float gbuf[2][128];
    if (tid < 32) hs[tid] = 0.0f;
    float c = 0.0f;
    __syncthreads();

    const float* xq = g_xp + (size_t)(d * 64 + b) * 1024 * 128 + g * 32 + hh;
    float cur = xq[0];
    float nxt = xq[128];

    float* outp = hout + (size_t)b * 1024 * 64 + d * 32 + hh;

    for (int s = 0; s < 1024; s++){
        float nn = xq[(size_t)(s + 2) * 128];   // g_xp padded: tail reads harmless

        U64 a0 = 0ull, a1 = 0ull;
        const ulonglong2* h2 = (const ulonglong2*)hs;
        #pragma unroll
        for (int r = 0; r < 8; r++){
            ulonglong2 hv = h2[r];
            ffma2(a0, hv.x, wp[2*r]);
            ffma2(a1, hv.y, wp[2*r+1]);
        }
        float pre = cur + sum2(add2(a0, a1));
        float act = (g == 2) ? tanha(pre) : siga(pre);
        float* gb = gbuf[s & 1];
        gb[g * 32 + hh] = act;
        __syncthreads();

        float iv = gb[hh];
        float fv = gb[32 + hh];
        float gv = gb[64 + hh];
        float ov = gb[96 + hh];
        c = fmaf(fv, c, iv * gv);
        float hval = ov * tanha(c);
        hs[hh] = hval;
        __syncwarp();
        if (g == 0){
            int tout = d ? (1023 - s) : s;
            outp[(size_t)tout * 64] = hval;
        }
        cur = nxt; nxt = nn;
    }
}

// ---------------- fc via mma.sync bf16 3-term split (fc1 & fc2) ----------------
// part[split][64][N] : D[64 batch, 128 wrow-tile] = X[64,K] * W[N,K]^T slice
#define MB_WH 0
#define MB_WL 8192
#define MB_XH 16384
#define MB_XL 20480
#define MB_BUF 24576

__global__ void __launch_bounds__(128) fc_mma_kernel(
    const float* __restrict__ W, const float* __restrict__ Xg,
    float* __restrict__ part, int K, int N, int nchunks)
{
    __shared__ __align__(128) char smb[2 * MB_BUF];  // 48KB
    const int tid  = threadIdx.x;
    const int lane = tid & 31;
    const int wid  = tid >> 5;
    const int m0out  = blockIdx.x * 128;
    const int kstart = blockIdx.y * (nchunks * 32);

    const int kq    = tid & 7;     // float4 index in 32-k row
    const int rbase = tid >> 3;    // 0..15

    const float* wg = W  + (size_t)(m0out + rbase) * K + kstart + kq * 4;
    const float* xg = Xg + (size_t)rbase * K + kstart + kq * 4;

    const uint32_t sb = smem_u32(smb);

    const int arow = wid * 16 + ((lane >> 3) & 1) * 8 + (lane & 7);
    const int asw  = (arow >> 1) & 3;
    const int akb  = lane >> 4;
    const uint32_t aoff = (uint32_t)(arow * 64);
    const int brow = ((lane >> 4) & 1) * 8 + (lane & 7);
    const int bsw  = (brow >> 1) & 3;
    const int bkb  = (lane >> 3) & 1;
    const uint32_t boff = (uint32_t)(brow * 64);

    float acc[16][4];
    #pragma unroll
    for (int i = 0; i < 16; i++)
        #pragma unroll
        for (int j = 0; j < 4; j++) acc[i][j] = 0.0f;

    float4 wv[8], xv[4];
    #pragma unroll
    for (int i = 0; i < 8; i++) wv[i] = *(const float4*)(wg + (size_t)i * 16 * K);
    #pragma unroll
    for (int i = 0; i < 4; i++) xv[i] = *(const float4*)(xg + (size_t)i * 16 * K);

    const int so_base = (kq & 1) * 8;
    for (int ch = 0; ch < nchunks; ch++){
        char* bufc = smb + (ch & 1) * MB_BUF;
        #pragma unroll
        for (int i = 0; i < 8; i++){
            float4 v = wv[i];
            int row = rbase + i * 16;
            uint32_t h0 = cvt_bf2(v.x, v.y);
            uint32_t l0 = cvt_bf2(v.x - __uint_as_float(h0 << 16),
                                  v.y - __uint_as_float(h0 & 0xFFFF0000u));
            uint32_t h1 = cvt_bf2(v.z, v.w);
            uint32_t l1 = cvt_bf2(v.z - __uint_as_float(h1 << 16),
                                  v.w - __uint_as_float(h1 & 0xFFFF0000u));
            int so = row * 64 + ((((kq >> 1) ^ ((row >> 1) & 3)) << 4) | so_base);
            *(uint2*)(bufc + MB_WH + so) = make_uint2(h0, h1);
            *(uint2*)(bufc + MB_WL + so) = make_uint2(l0, l1);
        }
        #pragma unroll
        for (int i = 0; i < 4; i++){
            float4 v = xv[i];
            int row = rbase + i * 16;
            uint32_t h0 = cvt_bf2(v.x, v.y);
            uint32_t l0 = cvt_bf2(v.x - __uint_as_float(h0 << 16),
                                  v.y - __uint_as_float(h0 & 0xFFFF0000u));
            uint32_t h1 = cvt_bf2(v.z, v.w);
            uint32_t l1 = cvt_bf2(v.z - __uint_as_float(h1 << 16),
                                  v.w - __uint_as_float(h1 & 0xFFFF0000u));
            int so = row * 64 + ((((kq >> 1) ^ ((row >> 1) & 3)) << 4) | so_base);
            *(uint2*)(bufc + MB_XH + so) = make_uint2(h0, h1);
            *(uint2*)(bufc + MB_XL + so) = make_uint2(l0, l1);
        }
        __syncthreads();

        if (ch + 1 < nchunks){
            #pragma unroll
            for (int i = 0; i < 8; i++) wv[i] = *(const float4*)(wg + (size_t)i * 16 * K + (ch + 1) * 32);
            #pragma unroll
            for (int i = 0; i < 4; i++) xv[i] = *(const float4*)(xg + (size_t)i * 16 * K + (ch + 1) * 32);
        }

        const uint32_t sbuf = sb + (ch & 1) * MB_BUF;
        #pragma unroll
        for (int kt = 0; kt < 2; kt++){
            uint32_t ahi[4], alo[4];
            uint32_t aaddr = sbuf + MB_XH + aoff + (uint32_t)((((kt << 1) | akb) ^ asw) << 4);
            ldm4(ahi, aaddr);
            ldm4(alo, aaddr + (MB_XL - MB_XH));
            #pragma unroll
            for (int ntp = 0; ntp < 8; ntp++){
                uint32_t bhi[4], blo[4];
                uint32_t baddr = sbuf + MB_WH + (uint32_t)(ntp * 1024) + boff
                               + (uint32_t)((((kt << 1) | bkb) ^ bsw) << 4);
                ldm4(bhi, baddr);
                ldm4(blo, baddr + (MB_WL - MB_WH));
                mma_bf(acc[2*ntp],   ahi, bhi[0], bhi[1]);
                mma_bf(acc[2*ntp],   alo, bhi[0], bhi[1]);
                mma_bf(acc[2*ntp],   ahi, blo[0], blo[1]);
                mma_bf(acc[2*ntp+1], ahi, bhi[2], bhi[3]);
                mma_bf(acc[2*ntp+1], alo, bhi[2], bhi[3]);
                mma_bf(acc[2*ntp+1], ahi, blo[2], blo[3]);
            }
        }
        __syncthreads();
    }

    {
        int bat  = wid * 16 + (lane >> 2);
        int colb = m0out + (lane & 3) * 2;
        float* d0 = part + ((size_t)blockIdx.y * 64 + bat) * N + colb;
        float* d1 = d0 + (size_t)8 * N;
        #pragma unroll
        for (int nt = 0; nt < 16; nt++){
            *(float2*)(d0 + nt * 8) = make_float2(acc[nt][0], acc[nt][1]);
            *(float2*)(d1 + nt * 8) = make_float2(acc[nt][2], acc[nt][3]);
        }
    }
}

// ---------------- split-K reductions ----------------
__global__ void reduce1_kernel(const float* __restrict__ bias){
    int i = blockIdx.x * 256 + threadIdx.x;   // 131072
    int m = i & 2047, b = i >> 11;
    float acc = bias[m];
    #pragma unroll
    for (int s = 0; s < 64; s++) acc += g_part1[((size_t)s * 64 + b) * 2048 + m];
    g_hidden[i] = fmaxf(acc, 0.0f);
}

__global__ void reduce2_kernel(const float* __restrict__ bias, float* __restrict__ out){
    int i = blockIdx.x * 256 + threadIdx.x;   // 589824
    int n = i % 9216, b = i / 9216;
    float acc = bias[n];
    #pragma unroll
    for (int s = 0; s < 4; s++) acc += g_part2[((size_t)s * 64 + b) * 9216 + n];
    out[i] = acc;
}

// ---------------- launcher ----------------
extern "C" void kernel_launch(void* const* d_in, const int* in_sizes, int n_in,
                              void* d_out, int out_size)
{
    const float* x     = (const float*)d_in[0];
    const float* wih0  = (const float*)d_in[1];
    const float* whh0  = (const float*)d_in[2];
    const float* bih0  = (const float*)d_in[3];
    const float* bhh0  = (const float*)d_in[4];
    const float* wih0r = (const float*)d_in[5];
    const float* whh0r = (const float*)d_in[6];
    const float* bih0r = (const float*)d_in[7];
    const float* bhh0r = (const float*)d_in[8];
    const float* wih1  = (const float*)d_in[9];
    const float* whh1  = (const float*)d_in[10];
    const float* bih1  = (const float*)d_in[11];
    const float* bhh1  = (const float*)d_in[12];
    const float* wih1r = (const float*)d_in[13];
    const float* whh1r = (const float*)d_in[14];
    const float* bih1r = (const float*)d_in[15];
    const float* bhh1r = (const float*)d_in[16];
    const float* fc1w  = (const float*)d_in[17];
    const float* fc1b  = (const float*)d_in[18];
    const float* fc2w  = (const float*)d_in[19];
    const float* fc2b  = (const float*)d_in[20];
    float* out = (float*)d_out;

    float* d_h1;     cudaGetSymbolAddress((void**)&d_h1,     g_h1);
    float* d_hidden; cudaGetSymbolAddress((void**)&d_hidden, g_hidden);
    float* d_part1;  cudaGetSymbolAddress((void**)&d_part1,  g_part1);
    float* d_part2;  cudaGetSymbolAddress((void**)&d_part2,  g_part2);

    xproj0_kernel<<<dim3(16, 64, 2), 256>>>(x, wih0, bih0, bhh0, wih0r, bih0r, bhh0r);
    lstm_kernel<<<128, 128>>>(whh0, whh0r, 0);
    xproj1_kernel<<<dim3(16, 64, 2), 256>>>(wih1, bih1, bhh1, wih1r, bih1r, bhh1r);
    lstm_kernel<<<128, 128>>>(whh1, whh1r, 1);

    // fc1: grid (16 wrow-tiles of 128, 64 k-splits of 1024 => 32 chunks)
    fc_mma_kernel<<<dim3(16, 64), 128>>>(fc1w, d_h1, d_part1, 65536, 2048, 32);
    reduce1_kernel<<<512, 256>>>(fc1b);

    // fc2: grid (72 wrow-tiles of 128, 4 k-splits of 512 => 16 chunks)
    fc_mma_kernel<<<dim3(72, 4), 128>>>(fc2w, d_hidden, d_part2, 2048, 9216, 16);
    reduce2_kernel<<<2304, 256>>>(fc2b, out);
}

// round 13
// speedup vs baseline: 2.2324x; 1.1769x over previous
#include <cuda_runtime.h>
#include <cstdint>

typedef unsigned long long U64;

// ---------------- static device scratch ----------------
__device__ float g_xp[16778240];   // [2][64][1024][128] + pad (deep-prefetch overrun)
__device__ float g_h0[4194304];    // [64][1024][64]
__device__ float g_h1[4194304];    // [64][1024][64]
__device__ float g_part1[8388608]; // [64][64][2048] fc1 split-K partials
__device__ float g_hidden[131072]; // [64][2048]
__device__ float g_part2[2359296]; // [4][64][9216] fc2 split-K partials

// ---------------- helpers ----------------
__device__ __forceinline__ void ffma2(U64 &acc, U64 a, U64 b){
    asm("fma.rn.f32x2 %0, %1, %2, %0;" : "+l"(acc) : "l"(a), "l"(b));
}
__device__ __forceinline__ U64 add2(U64 a, U64 b){
    U64 r; asm("add.rn.f32x2 %0, %1, %2;" : "=l"(r) : "l"(a), "l"(b)); return r;
}
__device__ __forceinline__ float2 unpk(U64 v){
    float2 r; asm("mov.b64 {%0, %1}, %2;" : "=f"(r.x), "=f"(r.y) : "l"(v)); return r;
}
__device__ __forceinline__ float sum2(U64 v){ float2 r = unpk(v); return r.x + r.y; }
__device__ __forceinline__ float tanha(float x){ float r; asm("tanh.approx.f32 %0, %1;" : "=f"(r) : "f"(x)); return r; }
__device__ __forceinline__ float siga (float x){ return fmaf(0.5f, tanha(0.5f * x), 0.5f); }

// cvt: word = { hi16: bf16(b), lo16: bf16(a) }
__device__ __forceinline__ uint32_t cvt_bf2(float a, float b){
    uint32_t r; asm("cvt.rn.bf16x2.f32 %0, %1, %2;" : "=r"(r) : "f"(b), "f"(a)); return r;
}
__device__ __forceinline__ uint32_t smem_u32(const void* p){
    uint32_t a; asm("{ .reg .u64 t; cvta.to.shared.u64 t, %1; cvt.u32.u64 %0, t; }" : "=r"(a) : "l"(p));
    return a;
}
__device__ __forceinline__ void ldm4(uint32_t* r, uint32_t addr){
    asm volatile("ldmatrix.sync.aligned.m8n8.x4.shared.b16 {%0,%1,%2,%3}, [%4];"
        : "=r"(r[0]), "=r"(r[1]), "=r"(r[2]), "=r"(r[3]) : "r"(addr));
}
__device__ __forceinline__ void mma_bf(float (&d)[4], const uint32_t* a, uint32_t b0, uint32_t b1){
    asm volatile("mma.sync.aligned.m16n8k16.row.col.f32.bf16.bf16.f32 "
        "{%0,%1,%2,%3}, {%4,%5,%6,%7}, {%8,%9}, {%0,%1,%2,%3};"
        : "+f"(d[0]), "+f"(d[1]), "+f"(d[2]), "+f"(d[3])
        : "r"(a[0]), "r"(a[1]), "r"(a[2]), "r"(a[3]), "r"(b0), "r"(b1));
}

#define TW 132   // padded smem row stride (floats) for xproj kernels

// ---------------- xproj layer 0: tiled, K=9 ----------------
__global__ void __launch_bounds__(256) xproj0_kernel(const float* __restrict__ x,
    const float* __restrict__ wf, const float* __restrict__ bif, const float* __restrict__ bhf,
    const float* __restrict__ wr, const float* __restrict__ bir, const float* __restrict__ bhr)
{
    __shared__ float ws[9 * TW];
    __shared__ float fs[9 * TW];
    const int tid = threadIdx.x;
    const int s0 = blockIdx.x * 64;
    const int b  = blockIdx.y;
    const int d  = blockIdx.z;
    const float* w  = d ? wr : wf;
    const float* bi = d ? bir : bif;
    const float* bh = d ? bhr : bhf;

    if (tid < 128){
        const float* src = w + tid * 9;
        #pragma unroll
        for (int k = 0; k < 9; k++) ws[k * TW + tid] = src[k];
    } else if (tid < 192){
        int r = tid - 128;
        int s = s0 + r;
        int tsrc = d ? (1023 - s) : s;
        const float* src = x + ((size_t)b * 1024 + tsrc) * 9;
        #pragma unroll
        for (int k = 0; k < 9; k++){
            float v = src[k];
            *(float2*)&fs[k * TW + 2 * r] = make_float2(v, v);
        }
    }
    __syncthreads();

    const int nq = tid & 15;
    const int bq = tid >> 4;
    U64 acc[4][4];
    #pragma unroll
    for (int i = 0; i < 4; i++)
        #pragma unroll
        for (int j = 0; j < 4; j++) acc[i][j] = 0ull;

    #pragma unroll
    for (int kk = 0; kk < 9; kk++){
        ulonglong2 wa = *(const ulonglong2*)&ws[kk*TW + nq*4];
        ulonglong2 wb = *(const ulonglong2*)&ws[kk*TW + 64 + nq*4];
        ulonglong2 xa = *(const ulonglong2*)&fs[kk*TW + bq*8];
        ulonglong2 xc = *(const ulonglong2*)&fs[kk*TW + bq*8 + 4];
        U64 xv0 = xa.x, xv1 = xa.y, xv2 = xc.x, xv3 = xc.y;
        ffma2(acc[0][0], xv0, wa.x); ffma2(acc[0][1], xv0, wa.y);
        ffma2(acc[0][2], xv0, wb.x); ffma2(acc[0][3], xv0, wb.y);
        ffma2(acc[1][0], xv1, wa.x); ffma2(acc[1][1], xv1, wa.y);
        ffma2(acc[1][2], xv1, wb.x); ffma2(acc[1][3], xv1, wb.y);
        ffma2(acc[2][0], xv2, wa.x); ffma2(acc[2][1], xv2, wa.y);
        ffma2(acc[2][2], xv2, wb.x); ffma2(acc[2][3], xv2, wb.y);
        ffma2(acc[3][0], xv3, wa.x); ffma2(acc[3][1], xv3, wa.y);
        ffma2(acc[3][2], xv3, wb.x); ffma2(acc[3][3], xv3, wb.y);
    }

    int j0 = nq * 4, j1 = 64 + nq * 4;
    float bv[8];
    #pragma unroll
    for (int q = 0; q < 4; q++){ bv[q] = bi[j0+q] + bh[j0+q]; bv[4+q] = bi[j1+q] + bh[j1+q]; }

    float* base = g_xp + ((size_t)(d * 64 + b) * 1024 + s0) * 128;
    #pragma unroll
    for (int b4 = 0; b4 < 4; b4++){
        float* dst = base + (size_t)(bq * 4 + b4) * 128;
        float2 v0 = unpk(acc[b4][0]); v0.x += bv[0]; v0.y += bv[1];
        float2 v1 = unpk(acc[b4][1]); v1.x += bv[2]; v1.y += bv[3];
        float2 v2 = unpk(acc[b4][2]); v2.x += bv[4]; v2.y += bv[5];
        float2 v3 = unpk(acc[b4][3]); v3.x += bv[6]; v3.y += bv[7];
        *(float2*)(dst + j0)     = v0;
        *(float2*)(dst + j0 + 2) = v1;
        *(float2*)(dst + j1)     = v2;
        *(float2*)(dst + j1 + 2) = v3;
    }
}

// ---------------- xproj layer 1: tiled GEMM, K=64 ----------------
__global__ void __launch_bounds__(256) xproj1_kernel(
    const float* __restrict__ wf, const float* __restrict__ bif, const float* __restrict__ bhf,
    const float* __restrict__ wr, const float* __restrict__ bir, const float* __restrict__ bhr)
{
    __shared__ float ws[32 * TW];
    __shared__ float fs[32 * TW];
    const int tid = threadIdx.x;
    const int s0 = blockIdx.x * 64;
    const int b  = blockIdx.y;
    const int d  = blockIdx.z;
    const float* w  = d ? wr : wf;
    const float* bi = d ? bir : bif;
    const float* bh = d ? bhr : bhf;

    const int sn  = tid & 127, skq = tid >> 7;
    const int xr  = tid & 63,  xkq = tid >> 6;
    int s = s0 + xr;
    int tsrc = d ? (1023 - s) : s;
    const float* wptr = w + sn * 64 + skq * 16;
    const float* hptr = g_h0 + ((size_t)b * 1024 + tsrc) * 64 + xkq * 8;

    const int nq = tid & 15;
    const int bq = tid >> 4;
    U64 acc[4][4];
    #pragma unroll
    for (int i = 0; i < 4; i++)
        #pragma unroll
        for (int j = 0; j < 4; j++) acc[i][j] = 0ull;

    #pragma unroll
    for (int ch = 0; ch < 2; ch++){
        if (ch){ __syncthreads(); }
        {
            const float4* src = (const float4*)(wptr + ch * 32);
            float4 v0 = src[0], v1 = src[1], v2 = src[2], v3 = src[3];
            int kb = skq * 16;
            ws[(kb+ 0)*TW + sn] = v0.x; ws[(kb+ 1)*TW + sn] = v0.y;
            ws[(kb+ 2)*TW + sn] = v0.z; ws[(kb+ 3)*TW + sn] = v0.w;
            ws[(kb+ 4)*TW + sn] = v1.x; ws[(kb+ 5)*TW + sn] = v1.y;
            ws[(kb+ 6)*TW + sn] = v1.z; ws[(kb+ 7)*TW + sn] = v1.w;
            ws[(kb+ 8)*TW + sn] = v2.x; ws[(kb+ 9)*TW + sn] = v2.y;
            ws[(kb+10)*TW + sn] = v2.z; ws[(kb+11)*TW + sn] = v2.w;
            ws[(kb+12)*TW + sn] = v3.x; ws[(kb+13)*TW + sn] = v3.y;
            ws[(kb+14)*TW + sn] = v3.z; ws[(kb+15)*TW + sn] = v3.w;
        }
        {
            const float4* src = (const float4*)(hptr + ch * 32);
            float4 u0 = src[0], u1 = src[1];
            int kb = xkq * 8;
            *(float2*)&fs[(kb+0)*TW + 2*xr] = make_float2(u0.x, u0.x);
            *(float2*)&fs[(kb+1)*TW + 2*xr] = make_float2(u0.y, u0.y);
            *(float2*)&fs[(kb+2)*TW + 2*xr] = make_float2(u0.z, u0.z);
            *(float2*)&fs[(kb+3)*TW + 2*xr] = make_float2(u0.w, u0.w);
            *(float2*)&fs[(kb+4)*TW + 2*xr] = make_float2(u1.x, u1.x);
            *(float2*)&fs[(kb+5)*TW + 2*xr] = make_float2(u1.y, u1.y);
            *(float2*)&fs[(kb+6)*TW + 2*xr] = make_float2(u1.z, u1.z);
            *(float2*)&fs[(kb+7)*TW + 2*xr] = make_float2(u1.w, u1.w);
        }
        __syncthreads();
        #pragma unroll
        for (int kk = 0; kk < 32; kk++){
            ulonglong2 wa = *(const ulonglong2*)&ws[kk*TW + nq*4];
            ulonglong2 wb = *(const ulonglong2*)&ws[kk*TW + 64 + nq*4];
            ulonglong2 xa = *(const ulonglong2*)&fs[kk*TW + bq*8];
            ulonglong2 xc = *(const ulonglong2*)&fs[kk*TW + bq*8 + 4];
            U64 xv0 = xa.x, xv1 = xa.y, xv2 = xc.x, xv3 = xc.y;
            ffma2(acc[0][0], xv0, wa.x); ffma2(acc[0][1], xv0, wa.y);
            ffma2(acc[0][2], xv0, wb.x); ffma2(acc[0][3], xv0, wb.y);
            ffma2(acc[1][0], xv1, wa.x); ffma2(acc[1][1], xv1, wa.y);
            ffma2(acc[1][2], xv1, wb.x); ffma2(acc[1][3], xv1, wb.y);
            ffma2(acc[2][0], xv2, wa.x); ffma2(acc[2][1], xv2, wa.y);
            ffma2(acc[2][2], xv2, wb.x); ffma2(acc[2][3], xv2, wb.y);
            ffma2(acc[3][0], xv3, wa.x); ffma2(acc[3][1], xv3, wa.y);
            ffma2(acc[3][2], xv3, wb.x); ffma2(acc[3][3], xv3, wb.y);
        }
    }

    int j0 = nq * 4, j1 = 64 + nq * 4;
    float bv[8];
    #pragma unroll
    for (int q = 0; q < 4; q++){ bv[q] = bi[j0+q] + bh[j0+q]; bv[4+q] = bi[j1+q] + bh[j1+q]; }

    float* base = g_xp + ((size_t)(d * 64 + b) * 1024 + s0) * 128;
    #pragma unroll
    for (int b4 = 0; b4 < 4; b4++){
        float* dst = base + (size_t)(bq * 4 + b4) * 128;
        float2 v0 = unpk(acc[b4][0]); v0.x += bv[0]; v0.y += bv[1];
        float2 v1 = unpk(acc[b4][1]); v1.x += bv[2]; v1.y += bv[3];
        float2 v2 = unpk(acc[b4][2]); v2.x += bv[4]; v2.y += bv[5];
        float2 v3 = unpk(acc[b4][3]); v3.x += bv[6]; v3.y += bv[7];
        *(float2*)(dst + j0)     = v0;
        *(float2*)(dst + j0 + 2) = v1;
        *(float2*)(dst + j1)     = v2;
        *(float2*)(dst + j1 + 2) = v3;
    }
}

// ---------------- LSTM: 4 warps/(dir,batch), 4-deep xp prefetch pipeline ----------------
__global__ void __launch_bounds__(128, 1) lstm_kernel(
    const float* __restrict__ whh_f, const float* __restrict__ whh_r, int outsel)
{
    const int blk = blockIdx.x;
    const int d = blk >> 6, b = blk & 63;
    const int tid = threadIdx.x;
    const int g = tid >> 5;
    const int hh = tid & 31;
    float* hout = outsel ? g_h1 : g_h0;
    const float* whh = d ? whh_r : whh_f;

    U64 wp[16];
    {
        const ulonglong2* wr2 = (const ulonglong2*)(whh + (g * 32 + hh) * 32);
        #pragma unroll
        for (int r = 0; r < 8; r++){ ulonglong2 v = wr2[r]; wp[2*r] = v.x; wp[2*r+1] = v.y; }
    }

    __shared__ __align__(16) float hs[32];
    __shared__ __align__(16) float gbuf[2][128];
    if (tid < 32) hs[tid] = 0.0f;
    float c = 0.0f;
    __syncthreads();

    const float* xq = g_xp + (size_t)(d * 64 + b) * 1024 * 128 + g * 32 + hh;
    float* outp = hout + (size_t)b * 1024 * 64 + d * 32 + hh;

    // 4-deep prefetch pipeline: values for steps s..s+3 resident; loads for s+4..s+7 in flight
    float xa = xq[0], xb = xq[128], xc2 = xq[256], xd = xq[384];

    #define LSTM_STEP(SS, CUR, PARITY)                                        \
    {                                                                         \
        U64 a0 = 0ull, a1 = 0ull;                                             \
        const ulonglong2* h2 = (const ulonglong2*)hs;                         \
        _Pragma("unroll")                                                     \
        for (int r = 0; r < 8; r++){                                          \
            ulonglong2 hv = h2[r];                                            \
            ffma2(a0, hv.x, wp[2*r]);                                         \
            ffma2(a1, hv.y, wp[2*r+1]);                                       \
        }                                                                     \
        float pre = (CUR) + sum2(add2(a0, a1));                               \
        float act = (g == 2) ? tanha(pre) : siga(pre);                        \
        gbuf[PARITY][g * 32 + hh] = act;                                      \
        __syncthreads();                                                      \
        float iv = gbuf[PARITY][hh];                                          \
        float fv = gbuf[PARITY][32 + hh];                                     \
        float gv = gbuf[PARITY][64 + hh];                                     \
        float ov = gbuf[PARITY][96 + hh];                                     \
        c = fmaf(fv, c, iv * gv);                                             \
        float hval = ov * tanha(c);                                           \
        hs[hh] = hval;                                                        \
        __syncwarp();                                                         \
        if (g == 0){                                                          \
            int tout = d ? (1023 - (SS)) : (SS);                              \
            outp[(size_t)tout * 64] = hval;                                   \
        }                                                                     \
    }

    for (int s = 0; s < 1024; s += 4){
        // loads for steps s+4..s+7: ~4 full steps of slack before use
        const float* q = xq + (size_t)(s + 4) * 128;
        float na = q[0], nb = q[128], nc = q[256], nd = q[384];

        LSTM_STEP(s + 0, xa, 0)
        LSTM_STEP(s + 1, xb, 1)
        LSTM_STEP(s + 2, xc2, 0)
        LSTM_STEP(s + 3, xd, 1)

        xa = na; xb = nb; xc2 = nc; xd = nd;
    }
    #undef LSTM_STEP
}

// ---------------- fc via mma.sync bf16 3-term split (fc1 & fc2) ----------------
#define MB_WH 0
#define MB_WL 8192
#define MB_XH 16384
#define MB_XL 20480
#define MB_BUF 24576

__global__ void __launch_bounds__(128) fc_mma_kernel(
    const float* __restrict__ W, const float* __restrict__ Xg,
    float* __restrict__ part, int K, int N, int nchunks)
{
    __shared__ __align__(128) char smb[2 * MB_BUF];  // 48KB
    const int tid  = threadIdx.x;
    const int lane = tid & 31;
    const int wid  = tid >> 5;
    const int m0out  = blockIdx.x * 128;
    const int kstart = blockIdx.y * (nchunks * 32);

    const int kq    = tid & 7;
    const int rbase = tid >> 3;

    const float* wg = W  + (size_t)(m0out + rbase) * K + kstart + kq * 4;
    const float* xg = Xg + (size_t)rbase * K + kstart + kq * 4;

    const uint32_t sb = smem_u32(smb);

    const int arow = wid * 16 + ((lane >> 3) & 1) * 8 + (lane & 7);
    const int asw  = (arow >> 1) & 3;
    const int akb  = lane >> 4;
    const uint32_t aoff = (uint32_t)(arow * 64);
    const int brow = ((lane >> 4) & 1) * 8 + (lane & 7);
    const int bsw  = (brow >> 1) & 3;
    const int bkb  = (lane >> 3) & 1;
    const uint32_t boff = (uint32_t)(brow * 64);

    float acc[16][4];
    #pragma unroll
    for (int i = 0; i < 16; i++)
        #pragma unroll
        for (int j = 0; j < 4; j++) acc[i][j] = 0.0f;

    float4 wv[8], xv[4];
    #pragma unroll
    for (int i = 0; i < 8; i++) wv[i] = *(const float4*)(wg + (size_t)i * 16 * K);
    #pragma unroll
    for (int i = 0; i < 4; i++) xv[i] = *(const float4*)(xg + (size_t)i * 16 * K);

    const int so_base = (kq & 1) * 8;
    for (int ch = 0; ch < nchunks; ch++){
        char* bufc = smb + (ch & 1) * MB_BUF;
        #pragma unroll
        for (int i = 0; i < 8; i++){
            float4 v = wv[i];
            int row = rbase + i * 16;
            uint32_t h0 = cvt_bf2(v.x, v.y);
            uint32_t l0 = cvt_bf2(v.x - __uint_as_float(h0 << 16),
                                  v.y - __uint_as_float(h0 & 0xFFFF0000u));
            uint32_t h1 = cvt_bf2(v.z, v.w);
            uint32_t l1 = cvt_bf2(v.z - __uint_as_float(h1 << 16),
                                  v.w - __uint_as_float(h1 & 0xFFFF0000u));
            int so = row * 64 + ((((kq >> 1) ^ ((row >> 1) & 3)) << 4) | so_base);
            *(uint2*)(bufc + MB_WH + so) = make_uint2(h0, h1);
            *(uint2*)(bufc + MB_WL + so) = make_uint2(l0, l1);
        }
        #pragma unroll
        for (int i = 0; i < 4; i++){
            float4 v = xv[i];
            int row = rbase + i * 16;
            uint32_t h0 = cvt_bf2(v.x, v.y);
            uint32_t l0 = cvt_bf2(v.x - __uint_as_float(h0 << 16),
                                  v.y - __uint_as_float(h0 & 0xFFFF0000u));
            uint32_t h1 = cvt_bf2(v.z, v.w);
            uint32_t l1 = cvt_bf2(v.z - __uint_as_float(h1 << 16),
                                  v.w - __uint_as_float(h1 & 0xFFFF0000u));
            int so = row * 64 + ((((kq >> 1) ^ ((row >> 1) & 3)) << 4) | so_base);
            *(uint2*)(bufc + MB_XH + so) = make_uint2(h0, h1);
            *(uint2*)(bufc + MB_XL + so) = make_uint2(l0, l1);
        }
        __syncthreads();

        if (ch + 1 < nchunks){
            #pragma unroll
            for (int i = 0; i < 8; i++) wv[i] = *(const float4*)(wg + (size_t)i * 16 * K + (ch + 1) * 32);
            #pragma unroll
            for (int i = 0; i < 4; i++) xv[i] = *(const float4*)(xg + (size_t)i * 16 * K + (ch + 1) * 32);
        }

        const uint32_t sbuf = sb + (ch & 1) * MB_BUF;
        #pragma unroll
        for (int kt = 0; kt < 2; kt++){
            uint32_t ahi[4], alo[4];
            uint32_t aaddr = sbuf + MB_XH + aoff + (uint32_t)((((kt << 1) | akb) ^ asw) << 4);
            ldm4(ahi, aaddr);
            ldm4(alo, aaddr + (MB_XL - MB_XH));
            #pragma unroll
            for (int ntp = 0; ntp < 8; ntp++){
                uint32_t bhi[4], blo[4];
                uint32_t baddr = sbuf + MB_WH + (uint32_t)(ntp * 1024) + boff
                               + (uint32_t)((((kt << 1) | bkb) ^ bsw) << 4);
                ldm4(bhi, baddr);
                ldm4(blo, baddr + (MB_WL - MB_WH));
                mma_bf(acc[2*ntp],   ahi, bhi[0], bhi[1]);
                mma_bf(acc[2*ntp],   alo, bhi[0], bhi[1]);
                mma_bf(acc[2*ntp],   ahi, blo[0], blo[1]);
                mma_bf(acc[2*ntp+1], ahi, bhi[2], bhi[3]);
                mma_bf(acc[2*ntp+1], alo, bhi[2], bhi[3]);
                mma_bf(acc[2*ntp+1], ahi, blo[2], blo[3]);
            }
        }
        __syncthreads();
    }

    {
        int bat  = wid * 16 + (lane >> 2);
        int colb = m0out + (lane & 3) * 2;
        float* d0 = part + ((size_t)blockIdx.y * 64 + bat) * N + colb;
        float* d1 = d0 + (size_t)8 * N;
        #pragma unroll
        for (int nt = 0; nt < 16; nt++){
            *(float2*)(d0 + nt * 8) = make_float2(acc[nt][0], acc[nt][1]);
            *(float2*)(d1 + nt * 8) = make_float2(acc[nt][2], acc[nt][3]);
        }
    }
}

// ---------------- split-K reductions ----------------
__global__ void reduce1_kernel(const float* __restrict__ bias){
    int i = blockIdx.x * 256 + threadIdx.x;   // 131072
    int m = i & 2047, b = i >> 11;
    float acc = bias[m];
    #pragma unroll
    for (int s = 0; s < 64; s++) acc += g_part1[((size_t)s * 64 + b) * 2048 + m];
    g_hidden[i] = fmaxf(acc, 0.0f);
}

__global__ void reduce2_kernel(const float* __restrict__ bias, float* __restrict__ out){
    int i = blockIdx.x * 256 + threadIdx.x;   // 589824
    int n = i % 9216, b = i / 9216;
    float acc = bias[n];
    #pragma unroll
    for (int s = 0; s < 4; s++) acc += g_part2[((size_t)s * 64 + b) * 9216 + n];
    out[i] = acc;
}

// ---------------- launcher ----------------
extern "C" void kernel_launch(void* const* d_in, const int* in_sizes, int n_in,
                              void* d_out, int out_size)
{
    const float* x     = (const float*)d_in[0];
    const float* wih0  = (const float*)d_in[1];
    const float* whh0  = (const float*)d_in[2];
    const float* bih0  = (const float*)d_in[3];
    const float* bhh0  = (const float*)d_in[4];
    const float* wih0r = (const float*)d_in[5];
    const float* whh0r = (const float*)d_in[6];
    const float* bih0r = (const float*)d_in[7];
    const float* bhh0r = (const float*)d_in[8];
    const float* wih1  = (const float*)d_in[9];
    const float* whh1  = (const float*)d_in[10];
    const float* bih1  = (const float*)d_in[11];
    const float* bhh1  = (const float*)d_in[12];
    const float* wih1r = (const float*)d_in[13];
    const float* whh1r = (const float*)d_in[14];
    const float* bih1r = (const float*)d_in[15];
    const float* bhh1r = (const float*)d_in[16];
    const float* fc1w  = (const float*)d_in[17];
    const float* fc1b  = (const float*)d_in[18];
    const float* fc2w  = (const float*)d_in[19];
    const float* fc2b  = (const float*)d_in[20];
    float* out = (float*)d_out;

    float* d_h1;     cudaGetSymbolAddress((void**)&d_h1,     g_h1);
    float* d_hidden; cudaGetSymbolAddress((void**)&d_hidden, g_hidden);
    float* d_part1;  cudaGetSymbolAddress((void**)&d_part1,  g_part1);
    float* d_part2;  cudaGetSymbolAddress((void**)&d_part2,  g_part2);

    xproj0_kernel<<<dim3(16, 64, 2), 256>>>(x, wih0, bih0, bhh0, wih0r, bih0r, bhh0r);
    lstm_kernel<<<128, 128>>>(whh0, whh0r, 0);
    xproj1_kernel<<<dim3(16, 64, 2), 256>>>(wih1, bih1, bhh1, wih1r, bih1r, bhh1r);
    lstm_kernel<<<128, 128>>>(whh1, whh1r, 1);

    // fc1: grid (16 wrow-tiles of 128, 64 k-splits of 1024 => 32 chunks)
    fc_mma_kernel<<<dim3(16, 64), 128>>>(fc1w, d_h1, d_part1, 65536, 2048, 32);
    reduce1_kernel<<<512, 256>>>(fc1b);

    // fc2: grid (72 wrow-tiles of 128, 4 k-splits of 512 => 16 chunks)
    fc_mma_kernel<<<dim3(72, 4), 128>>>(fc2w, d_hidden, d_part2, 2048, 9216, 16);
    reduce2_kernel<<<2304, 256>>>(fc2b, out);
}